// round 14
// baseline (speedup 1.0000x reference)
#include <cuda_runtime.h>
#include <cuda_bf16.h>
#include <math.h>

#define B_  32
#define S_  1024
#define E_  64
#define H_  4
#define HD_ 16
#define HID_ 256
#define AD_ 32
#define NS_ 64
#define NT_ (B_*S_)
#define QSCALE (0.25f * 1.4426950408889634f)

__device__ __align__(16) __nv_bfloat16 g_qh[B_*H_*S_*HD_];
__device__ __align__(16) __nv_bfloat16 g_kh[B_*H_*S_*HD_];
__device__ __align__(16) __nv_bfloat16 g_vt[B_*H_*HD_*S_];
__device__ __align__(16) __nv_bfloat16 g_ob[(size_t)NT_*E_];      // attn out, bf16
__device__ __align__(16) __nv_bfloat16 g_rv[(size_t)NT_*E_];      // read_vals bf16
__device__ __align__(16) __nv_bfloat16 g_hidb[(size_t)NT_*HID_];

__device__ __forceinline__ unsigned long long pk2(float lo, float hi) {
    unsigned long long r; asm("mov.b64 %0,{%1,%2};" : "=l"(r) : "f"(lo), "f"(hi)); return r;
}
__device__ __forceinline__ float2 upk2(unsigned long long v) {
    float2 f; asm("mov.b64 {%0,%1},%2;" : "=f"(f.x), "=f"(f.y) : "l"(v)); return f;
}
__device__ __forceinline__ unsigned long long ffma2_(unsigned long long a,
    unsigned long long b, unsigned long long c) {
    unsigned long long d;
    asm("fma.rn.f32x2 %0,%1,%2,%3;" : "=l"(d) : "l"(a), "l"(b), "l"(c)); return d;
}
__device__ __forceinline__ float ex2_(float x) {
    float y; asm("ex2.approx.f32 %0,%1;" : "=f"(y) : "f"(x)); return y;
}
__device__ __forceinline__ float gelu_(float v) {
    float u = v * (0.7978845608f + 0.0356774081f * v * v);
    float e = ex2_(u * 2.885390082f);
    float r; asm("rcp.approx.f32 %0,%1;" : "=f"(r) : "f"(1.f + e));
    return 0.5f * v * (2.f - 2.f*r);
}
__device__ __forceinline__ unsigned pbf_(float lo, float hi) {
    unsigned r; asm("cvt.rn.bf16x2.f32 %0,%1,%2;" : "=r"(r) : "f"(hi), "f"(lo)); return r;
}
__device__ __forceinline__ void mma16816(float& c0, float& c1, float& c2, float& c3,
    unsigned a0, unsigned a1, unsigned a2, unsigned a3, unsigned b0, unsigned b1) {
    asm volatile("mma.sync.aligned.m16n8k16.row.col.f32.bf16.bf16.f32 "
        "{%0,%1,%2,%3},{%4,%5,%6,%7},{%8,%9},{%0,%1,%2,%3};"
        : "+f"(c0), "+f"(c1), "+f"(c2), "+f"(c3)
        : "r"(a0), "r"(a1), "r"(a2), "r"(a3), "r"(b0), "r"(b1));
}

// ============ kernel 1: rmsnorm + QKV (bf16 out, V transposed) ============
__global__ void __launch_bounds__(256) qkv_kernel(
    const float* __restrict__ x, const float* __restrict__ nw,
    const float* __restrict__ wq, const float* __restrict__ wk,
    const float* __restrict__ wv)
{
    extern __shared__ float sm[];
    float* ws  = sm;                 // 3*64*66
    float* nws = ws + 3*4224;
    unsigned long long* htp_all = (unsigned long long*)(nws + 64);

    const int tid = threadIdx.x, lane = tid & 31, w = tid >> 5;

    for (int i = tid; i < 64*64; i += blockDim.x) {
        int e = i >> 6, j = i & 63;
        ws[0*4224 + e*66 + j] = wq[i];
        ws[1*4224 + e*66 + j] = wk[i];
        ws[2*4224 + e*66 + j] = wv[i];
    }
    if (tid < 64) nws[tid] = nw[tid];
    __syncthreads();

    unsigned long long* htp = htp_all + w*128;
    float* hview = (float*)htp;

    for (int chunk = blockIdx.x*8 + w; chunk < NT_/4; chunk += gridDim.x*8) {
        const int tok0 = chunk*4;
        #pragma unroll
        for (int t = 0; t < 4; t++) {
            float xa = x[(tok0+t)*64 + lane];
            float xb = x[(tok0+t)*64 + lane + 32];
            float ss = xa*xa + xb*xb;
            #pragma unroll
            for (int o = 16; o; o >>= 1) ss += __shfl_xor_sync(~0u, ss, o);
            float rinv = rsqrtf(ss * (1.f/64.f) + 1e-5f);
            int tp = t >> 1, c = t & 1;
            hview[(tp*64 + lane)*2 + c]      = xa * rinv * nws[lane];
            hview[(tp*64 + lane + 32)*2 + c] = xb * rinv * nws[lane + 32];
        }
        __syncwarp();

        unsigned long long acc[3][2][2];
        #pragma unroll
        for (int p = 0; p < 3; p++)
            #pragma unroll
            for (int r = 0; r < 2; r++) { acc[p][r][0] = 0ull; acc[p][r][1] = 0ull; }

        #pragma unroll 4
        for (int j = 0; j < 64; j += 2) {
            ulonglong2 h0 = *(const ulonglong2*)(htp + j);
            ulonglong2 h1 = *(const ulonglong2*)(htp + 64 + j);
            #pragma unroll
            for (int p = 0; p < 3; p++)
                #pragma unroll
                for (int r = 0; r < 2; r++) {
                    float2 wf = *(const float2*)(ws + p*4224 + (lane + r*32)*66 + j);
                    unsigned long long wx = pk2(wf.x, wf.x);
                    unsigned long long wy = pk2(wf.y, wf.y);
                    acc[p][r][0] = ffma2_(wx, h0.x, acc[p][r][0]);
                    acc[p][r][0] = ffma2_(wy, h0.y, acc[p][r][0]);
                    acc[p][r][1] = ffma2_(wx, h1.x, acc[p][r][1]);
                    acc[p][r][1] = ffma2_(wy, h1.y, acc[p][r][1]);
                }
        }

        const int b0 = tok0 >> 10, s0 = tok0 & 1023;
        #pragma unroll
        for (int r = 0; r < 2; r++) {
            int e = lane + r*32, hh = e >> 4, d = e & 15;
            size_t bhi = (size_t)(b0*H_ + hh);
            #pragma unroll
            for (int tp = 0; tp < 2; tp++) {
                int s = s0 + tp*2;
                float2 vq = upk2(acc[0][r][tp]);
                g_qh[(bhi*S_ + s  )*16 + d] = __float2bfloat16(vq.x * QSCALE);
                g_qh[(bhi*S_ + s+1)*16 + d] = __float2bfloat16(vq.y * QSCALE);
                float2 vk = upk2(acc[1][r][tp]);
                g_kh[(bhi*S_ + s  )*16 + d] = __float2bfloat16(vk.x);
                g_kh[(bhi*S_ + s+1)*16 + d] = __float2bfloat16(vk.y);
                float2 vv = upk2(acc[2][r][tp]);
                *(unsigned*)&g_vt[(bhi*16 + d)*S_ + s] = pbf_(vv.x, vv.y);
            }
        }
        __syncwarp();
    }
}

// ============ kernel 2: causal attention via bf16 HMMA (bf16 output) ============
__global__ void __launch_bounds__(128, 3) attn_kernel()
{
    const int bidx = blockIdx.x;
    const int qt = 7 - (bidx >> 7);          // heavy tiles first
    const int bh = bidx & 127;
    const int nk = (qt + 1) * 128;
    const int qbase = qt * 128;

    extern __shared__ char smc[];
    __nv_bfloat16* Ks = (__nv_bfloat16*)smc;                    // [nk][16]
    __nv_bfloat16* Vt = (__nv_bfloat16*)(smc + 32768);          // [16][1032]
    __nv_bfloat16* Qs = (__nv_bfloat16*)(smc + 32768 + 33024);  // [128][16]

    const int tid = threadIdx.x, lane = tid & 31, w = tid >> 5;

    {
        const uint4* src = (const uint4*)(g_kh + (size_t)bh * S_ * 16);
        uint4* dst = (uint4*)Ks;
        for (int i = tid; i < nk*2; i += 128) dst[i] = src[i];
    }
    {
        const uint4* src = (const uint4*)(g_qh + ((size_t)bh * S_ + qbase) * 16);
        uint4* dst = (uint4*)Qs;
        dst[tid] = src[tid];
        dst[tid + 128] = src[tid + 128];
    }
    for (int d = w; d < 16; d += 4) {
        const uint4* src = (const uint4*)(g_vt + ((size_t)bh*16 + d) * S_);
        uint4* dst = (uint4*)(Vt + d * 1032);
        for (int i = lane; i < nk/8; i += 32) dst[i] = src[i];
    }
    __syncthreads();

    const int g = lane >> 2, tg = lane & 3;

    unsigned qa[2][4];
    #pragma unroll
    for (int mf = 0; mf < 2; mf++) {
        int rr = w*32 + mf*16 + g;
        qa[mf][0] = *(const unsigned*)&Qs[ rr     *16 + 2*tg    ];
        qa[mf][1] = *(const unsigned*)&Qs[(rr + 8)*16 + 2*tg    ];
        qa[mf][2] = *(const unsigned*)&Qs[ rr     *16 + 2*tg + 8];
        qa[mf][3] = *(const unsigned*)&Qs[(rr + 8)*16 + 2*tg + 8];
    }

    float o[2][2][4];
    #pragma unroll
    for (int mf = 0; mf < 2; mf++)
        #pragma unroll
        for (int dh = 0; dh < 2; dh++)
            o[mf][dh][0] = o[mf][dh][1] = o[mf][dh][2] = o[mf][dh][3] = 0.f;
    float lsum[2][2] = {{0.f,0.f},{0.f,0.f}};

    auto step = [&](int j0, bool MASK) {
        unsigned kb[2][2], vb[2][2];
        #pragma unroll
        for (int kh = 0; kh < 2; kh++) {
            const __nv_bfloat16* kr = Ks + (j0 + kh*8 + g)*16 + 2*tg;
            kb[kh][0] = *(const unsigned*)kr;
            kb[kh][1] = *(const unsigned*)(kr + 8);
        }
        #pragma unroll
        for (int dh = 0; dh < 2; dh++) {
            const __nv_bfloat16* vr = Vt + (dh*8 + g)*1032 + j0 + 2*tg;
            vb[dh][0] = *(const unsigned*)vr;
            vb[dh][1] = *(const unsigned*)(vr + 8);
        }
        #pragma unroll
        for (int mf = 0; mf < 2; mf++) {
            float c[2][4];
            #pragma unroll
            for (int kh = 0; kh < 2; kh++) {
                c[kh][0] = c[kh][1] = c[kh][2] = c[kh][3] = 0.f;
                mma16816(c[kh][0], c[kh][1], c[kh][2], c[kh][3],
                         qa[mf][0], qa[mf][1], qa[mf][2], qa[mf][3],
                         kb[kh][0], kb[kh][1]);
            }
            const int r0 = qbase + w*32 + mf*16 + g, r1 = r0 + 8;
            float p[2][4];
            #pragma unroll
            for (int kh = 0; kh < 2; kh++) {
                int k0 = j0 + kh*8 + 2*tg;
                p[kh][0] = (!MASK || k0     <= r0) ? ex2_(c[kh][0]) : 0.f;
                p[kh][1] = (!MASK || k0 + 1 <= r0) ? ex2_(c[kh][1]) : 0.f;
                p[kh][2] = (!MASK || k0     <= r1) ? ex2_(c[kh][2]) : 0.f;
                p[kh][3] = (!MASK || k0 + 1 <= r1) ? ex2_(c[kh][3]) : 0.f;
            }
            lsum[mf][0] += (p[0][0] + p[0][1]) + (p[1][0] + p[1][1]);
            lsum[mf][1] += (p[0][2] + p[0][3]) + (p[1][2] + p[1][3]);
            unsigned pa0 = pbf_(p[0][0], p[0][1]);
            unsigned pa1 = pbf_(p[0][2], p[0][3]);
            unsigned pa2 = pbf_(p[1][0], p[1][1]);
            unsigned pa3 = pbf_(p[1][2], p[1][3]);
            #pragma unroll
            for (int dh = 0; dh < 2; dh++)
                mma16816(o[mf][dh][0], o[mf][dh][1], o[mf][dh][2], o[mf][dh][3],
                         pa0, pa1, pa2, pa3, vb[dh][0], vb[dh][1]);
        }
    };

    for (int j0 = 0; j0 < qbase; j0 += 16) step(j0, false);
    const int wlast = qbase + w*32 + 31;
    for (int j0 = qbase; j0 < nk; j0 += 16) {
        if (j0 > wlast) break;
        step(j0, true);
    }

    const int b = bh >> 2, h = bh & 3;
    #pragma unroll
    for (int mf = 0; mf < 2; mf++) {
        float l0 = lsum[mf][0], l1 = lsum[mf][1];
        l0 += __shfl_xor_sync(~0u, l0, 1); l0 += __shfl_xor_sync(~0u, l0, 2);
        l1 += __shfl_xor_sync(~0u, l1, 1); l1 += __shfl_xor_sync(~0u, l1, 2);
        float i0 = 1.f / l0, i1 = 1.f / l1;
        int r0 = qbase + w*32 + mf*16 + g;
        __nv_bfloat16* b0p = g_ob + (size_t)(b*S_ + r0)*64 + h*16;
        __nv_bfloat16* b1p = b0p + 8*64;
        *(unsigned*)(b0p + 2*tg)     = pbf_(o[mf][0][0]*i0, o[mf][0][1]*i0);
        *(unsigned*)(b0p + 8 + 2*tg) = pbf_(o[mf][1][0]*i0, o[mf][1][1]*i0);
        *(unsigned*)(b1p + 2*tg)     = pbf_(o[mf][0][2]*i1, o[mf][0][3]*i1);
        *(unsigned*)(b1p + 8 + 2*tg) = pbf_(o[mf][1][2]*i1, o[mf][1][3]*i1);
    }
}

// ============ kernel 3a: x1 = x + av@wo^T  (HMMA, 16 tok/warp) ============
__global__ void __launch_bounds__(256) mem1_kernel(
    const float* __restrict__ x, const float* __restrict__ wo,
    float* __restrict__ out)
{
    extern __shared__ char smc[];
    __nv_bfloat16* woB = (__nv_bfloat16*)smc;   // [64][72]

    const int tid = threadIdx.x, lane = tid & 31, w = tid >> 5;
    const int g = lane >> 2, tg = lane & 3;
    const int m0 = blockIdx.x*128 + w*16;

    for (int i = tid; i < 4096; i += 256)
        woB[(i >> 6)*72 + (i & 63)] = __float2bfloat16(wo[i]);
    __syncthreads();

    float c[8][4];
    #pragma unroll
    for (int nf = 0; nf < 8; nf++)
        c[nf][0] = c[nf][1] = c[nf][2] = c[nf][3] = 0.f;

    #pragma unroll
    for (int ks = 0; ks < 4; ks++) {
        const int k = ks*16 + 2*tg;
        const __nv_bfloat16* ar = g_ob + (size_t)(m0 + g)*64 + k;
        unsigned a0 = *(const unsigned*)ar;
        unsigned a1 = *(const unsigned*)(ar + 8*64);
        unsigned a2 = *(const unsigned*)(ar + 8);
        unsigned a3 = *(const unsigned*)(ar + 8*64 + 8);
        #pragma unroll
        for (int nf = 0; nf < 8; nf++) {
            const __nv_bfloat16* br = woB + (nf*8 + g)*72 + k;
            mma16816(c[nf][0], c[nf][1], c[nf][2], c[nf][3],
                     a0, a1, a2, a3,
                     *(const unsigned*)br, *(const unsigned*)(br + 8));
        }
    }

    const int r = m0 + g;
    #pragma unroll
    for (int nf = 0; nf < 8; nf++) {
        int e = nf*8 + 2*tg;
        float2 x0 = *(const float2*)&x[(size_t)r*64 + e];
        float2 x1 = *(const float2*)&x[(size_t)(r+8)*64 + e];
        *(float2*)&out[(size_t)r*64 + e] =
            make_float2(x0.x + c[nf][0], x0.y + c[nf][1]);
        *(float2*)&out[(size_t)(r+8)*64 + e] =
            make_float2(x1.x + c[nf][2], x1.y + c[nf][3]);
    }
}

// ============ kernel 3b: fp32 middle — rmsnorm/mq/l2norm/scores/top-8/gather ============
__global__ void __launch_bounds__(256) mem2_kernel(
    const float* __restrict__ mvals, const float* __restrict__ maddr,
    const float* __restrict__ mnw,   const float* __restrict__ mq,
    const float* __restrict__ out)
{
    extern __shared__ float sm[];
    float* mqT  = sm;              // [64][33]
    float* aT   = mqT + 2112;      // [32][65]
    float* mnws = aT + 2080;       // 64
    float* rows = mnws + 64;       // 8*96

    const int tid = threadIdx.x, lane = tid & 31, w = tid >> 5;

    for (int i = tid; i < AD_*E_; i += blockDim.x) {
        int a = i >> 6, e = i & 63;
        mqT[e*33 + a] = mq[i];
    }
    if (tid < 64) mnws[tid] = mnw[tid];
    if (tid < 64) {
        float ssum = 0.f, v[32];
        #pragma unroll
        for (int a = 0; a < 32; a++) { v[a] = maddr[tid*32 + a]; ssum += v[a]*v[a]; }
        float rn = 1.f / fmaxf(sqrtf(ssum), 1e-12f);
        #pragma unroll
        for (int a = 0; a < 32; a++) aT[a*65 + tid] = v[a] * rn;
    }
    __syncthreads();

    float* hrow = rows + w*96;
    float* qrow = hrow + 64;

    for (int tok = blockIdx.x*8 + w; tok < NT_; tok += gridDim.x*8) {
        const int b = tok >> 10;
        float x1a = out[(size_t)tok*64 + lane];
        float x1b = out[(size_t)tok*64 + lane + 32];
        float ss = x1a*x1a + x1b*x1b;
        #pragma unroll
        for (int o = 16; o; o >>= 1) ss += __shfl_xor_sync(~0u, ss, o);
        float rinv = rsqrtf(ss * (1.f/64.f) + 1e-5f);
        hrow[lane]      = x1a * rinv * mnws[lane];
        hrow[lane + 32] = x1b * rinv * mnws[lane + 32];
        __syncwarp();
        float qa = 0.f;
        #pragma unroll
        for (int e = 0; e < 64; e++) qa += hrow[e] * mqT[e*33 + lane];
        float qsm = qa*qa;
        #pragma unroll
        for (int o = 16; o; o >>= 1) qsm += __shfl_xor_sync(~0u, qsm, o);
        float rq = 1.f / fmaxf(sqrtf(qsm), 1e-12f);
        qrow[lane] = qa * rq;
        __syncwarp();
        float sc0 = 0.f, sc1 = 0.f;
        #pragma unroll
        for (int a = 0; a < 32; a++) {
            float qv = qrow[a];
            sc0 += qv * aT[a*65 + lane];
            sc1 += qv * aT[a*65 + lane + 32];
        }
        sc0 *= 4.f; sc1 *= 4.f;
        unsigned f0 = __float_as_uint(sc0);
        unsigned m0 = (f0 & 0x80000000u) ? ~f0 : (f0 | 0x80000000u);
        unsigned key0 = (m0 & 0xFFFFFFC0u) | (unsigned)(63 - lane);
        unsigned f1 = __float_as_uint(sc1);
        unsigned m1 = (f1 & 0x80000000u) ? ~f1 : (f1 | 0x80000000u);
        unsigned key1 = (m1 & 0xFFFFFFC0u) | (unsigned)(31 - lane);
        float tv[8]; int ti[8];
        #pragma unroll
        for (int k = 0; k < 8; k++) {
            unsigned loc = key0 > key1 ? key0 : key1;
            unsigned r = __reduce_max_sync(0xffffffffu, loc);
            int idx = 63 - (int)(r & 63u);
            float vsel = __shfl_sync(0xffffffffu, (idx >= 32) ? sc1 : sc0, idx & 31);
            tv[k] = vsel; ti[k] = idx;
            if (idx == lane)      key0 = 0u;
            if (idx == lane + 32) key1 = 0u;
        }
        float wsum = 0.f, wk8[8];
        #pragma unroll
        for (int k = 0; k < 8; k++) { wk8[k] = __expf(tv[k] - tv[0]); wsum += wk8[k]; }
        float winv = 1.f / wsum;
        const float* mb = mvals + b * NS_ * E_;
        float r0 = 0.f, r1 = 0.f;
        #pragma unroll
        for (int k = 0; k < 8; k++) {
            float wv = wk8[k] * winv;
            const float* mrow = mb + ti[k]*64;
            r0 += wv * mrow[lane];
            r1 += wv * mrow[lane + 32];
        }
        g_rv[(size_t)tok*64 + lane]      = __float2bfloat16(r0);
        g_rv[(size_t)tok*64 + lane + 32] = __float2bfloat16(r1);
    }
}

// ============ kernel 4: fused mo-proj + rmsnorm + FFN GEMM1 + GELU ============
// block = 128 tokens, 256 threads.
// Phase 1: x2 = out + rv@mo^T (HMMA, 8 warps x 16 tok) -> out + smem
// Phase 2: rmsnorm -> bf16 A tile
// Phase 3: GEMM1 (8 warps = 4 tok-quarter x 2 hid-half) + GELU -> g_hidb
__global__ void __launch_bounds__(256, 2) ffn1_kernel(
    const float* __restrict__ fnw, const float* __restrict__ b1,
    const float* __restrict__ mo,  const float* __restrict__ w1,
    float* __restrict__ out)
{
    extern __shared__ char smc[];
    __nv_bfloat16* w1s = (__nv_bfloat16*)smc;            // [256][72] 36864
    __nv_bfloat16* As  = (__nv_bfloat16*)(smc + 36864);  // [128][72] 18432
    __nv_bfloat16* moB = (__nv_bfloat16*)(smc + 55296);  // [64][72]   9216
    float* x2s = (float*)(smc + 64512);                  // [128][68] 34816
    float* b1s = (float*)(smc + 64512 + 34816);          // 256
    float* fns = b1s + 256;                              // 64

    const int tid = threadIdx.x, lane = tid & 31, w = tid >> 5;
    const int g = lane >> 2, tg = lane & 3;
    const int wm = w & 3, nh = w >> 2;
    const int tok0 = blockIdx.x * 128;

    for (int i = tid; i < HID_*E_; i += 256)
        w1s[(i >> 6)*72 + (i & 63)] = __float2bfloat16(w1[i]);
    for (int i = tid; i < E_*E_; i += 256)
        moB[(i >> 6)*72 + (i & 63)] = __float2bfloat16(mo[i]);
    b1s[tid] = b1[tid];
    if (tid < 64) fns[tid] = fnw[tid];
    __syncthreads();

    // ---- Phase 1: mo-proj HMMA (warp = 16 tokens) ----
    {
        const int m0 = tok0 + w*16;
        float c[8][4];
        #pragma unroll
        for (int nf = 0; nf < 8; nf++)
            c[nf][0] = c[nf][1] = c[nf][2] = c[nf][3] = 0.f;
        #pragma unroll
        for (int ks = 0; ks < 4; ks++) {
            const int k = ks*16 + 2*tg;
            const __nv_bfloat16* ar = g_rv + (size_t)(m0 + g)*64 + k;
            unsigned a0 = *(const unsigned*)ar;
            unsigned a1 = *(const unsigned*)(ar + 8*64);
            unsigned a2 = *(const unsigned*)(ar + 8);
            unsigned a3 = *(const unsigned*)(ar + 8*64 + 8);
            #pragma unroll
            for (int nf = 0; nf < 8; nf++) {
                const __nv_bfloat16* br = moB + (nf*8 + g)*72 + k;
                mma16816(c[nf][0], c[nf][1], c[nf][2], c[nf][3],
                         a0, a1, a2, a3,
                         *(const unsigned*)br, *(const unsigned*)(br + 8));
            }
        }
        const int r0 = m0 + g, r1 = r0 + 8;
        const int l0 = r0 - tok0, l1 = l0 + 8;
        #pragma unroll
        for (int nf = 0; nf < 8; nf++) {
            int e = nf*8 + 2*tg;
            float2 x0 = *(const float2*)&out[(size_t)r0*64 + e];
            float2 x1 = *(const float2*)&out[(size_t)r1*64 + e];
            float2 v0 = make_float2(x0.x + c[nf][0], x0.y + c[nf][1]);
            float2 v1 = make_float2(x1.x + c[nf][2], x1.y + c[nf][3]);
            *(float2*)&x2s[l0*68 + e] = v0;
            *(float2*)&x2s[l1*68 + e] = v1;
            *(float2*)&out[(size_t)r0*64 + e] = v0;
            *(float2*)&out[(size_t)r1*64 + e] = v1;
        }
    }
    __syncthreads();

    // ---- Phase 2: rmsnorm -> bf16 A tile ----
    if (tid < 128) {
        float4 v[16];
        float ss = 0.f;
        #pragma unroll
        for (int i = 0; i < 16; i++) {
            v[i] = *(const float4*)&x2s[tid*68 + 4*i];
            ss += v[i].x*v[i].x + v[i].y*v[i].y + v[i].z*v[i].z + v[i].w*v[i].w;
        }
        float rinv = rsqrtf(ss * (1.f/64.f) + 1e-5f);
        #pragma unroll
        for (int i = 0; i < 16; i++) {
            *(unsigned*)&As[tid*72 + 4*i]     = pbf_(v[i].x*rinv*fns[4*i],   v[i].y*rinv*fns[4*i+1]);
            *(unsigned*)&As[tid*72 + 4*i + 2] = pbf_(v[i].z*rinv*fns[4*i+2], v[i].w*rinv*fns[4*i+3]);
        }
    }
    __syncthreads();

    // ---- Phase 3: GEMM1 + GELU ----
    unsigned a[4][2][4];
    #pragma unroll
    for (int ks = 0; ks < 4; ks++)
        #pragma unroll
        for (int mf = 0; mf < 2; mf++) {
            int r = wm*32 + mf*16 + g;
            int k = ks*16 + 2*tg;
            a[ks][mf][0] = *(const unsigned*)&As[ r      *72 + k];
            a[ks][mf][1] = *(const unsigned*)&As[(r + 8) *72 + k];
            a[ks][mf][2] = *(const unsigned*)&As[ r      *72 + k + 8];
            a[ks][mf][3] = *(const unsigned*)&As[(r + 8) *72 + k + 8];
        }

    #pragma unroll
    for (int ch = 0; ch < 2; ch++) {
        const int n0 = nh*128 + ch*64;
        float c[2][8][4];
        #pragma unroll
        for (int mf = 0; mf < 2; mf++)
            #pragma unroll
            for (int nf = 0; nf < 8; nf++)
                c[mf][nf][0] = c[mf][nf][1] = c[mf][nf][2] = c[mf][nf][3] = 0.f;

        #pragma unroll
        for (int ks = 0; ks < 4; ks++) {
            #pragma unroll
            for (int nf = 0; nf < 8; nf++) {
                const __nv_bfloat16* br = w1s + (n0 + nf*8 + g)*72 + ks*16 + 2*tg;
                unsigned b0 = *(const unsigned*)br;
                unsigned bq = *(const unsigned*)(br + 8);
                #pragma unroll
                for (int mf = 0; mf < 2; mf++)
                    mma16816(c[mf][nf][0], c[mf][nf][1], c[mf][nf][2], c[mf][nf][3],
                             a[ks][mf][0], a[ks][mf][1], a[ks][mf][2], a[ks][mf][3],
                             b0, bq);
            }
        }

        #pragma unroll
        for (int mf = 0; mf < 2; mf++) {
            const int r = tok0 + wm*32 + mf*16 + g;
            #pragma unroll
            for (int nf = 0; nf < 8; nf++) {
                int e = n0 + nf*8 + 2*tg;
                float be0 = b1s[e], be1 = b1s[e+1];
                *(unsigned*)&g_hidb[(size_t)r*256 + e] =
                    pbf_(gelu_(c[mf][nf][0] + be0), gelu_(c[mf][nf][1] + be1));
                *(unsigned*)&g_hidb[(size_t)(r+8)*256 + e] =
                    pbf_(gelu_(c[mf][nf][2] + be0), gelu_(c[mf][nf][3] + be1));
            }
        }
    }
}

// ============ kernel 5: FFN GEMM2 via HMMA + residual ============
__global__ void __launch_bounds__(128, 4) ffn2_kernel(
    const float* __restrict__ b2, const float* __restrict__ w2,
    float* __restrict__ out)
{
    extern __shared__ char smc[];
    __nv_bfloat16* w2s = (__nv_bfloat16*)smc;   // [64][264]
    float* b2s = (float*)(smc + 64*264*2);

    const int tid = threadIdx.x, lane = tid & 31, w = tid >> 5;
    const int g = lane >> 2, tg = lane & 3;
    const int tok0 = blockIdx.x * 128;

    for (int i = tid; i < E_*HID_; i += 128)
        w2s[(i >> 8)*264 + (i & 255)] = __float2bfloat16(w2[i]);
    if (tid < 64) b2s[tid] = b2[tid];
    __syncthreads();

    float c[2][8][4];
    #pragma unroll
    for (int mf = 0; mf < 2; mf++)
        #pragma unroll
        for (int nf = 0; nf < 8; nf++)
            c[mf][nf][0] = c[mf][nf][1] = c[mf][nf][2] = c[mf][nf][3] = 0.f;

    const int m0 = tok0 + w*32;
    #pragma unroll 4
    for (int ks = 0; ks < 16; ks++) {
        const int k = ks*16 + 2*tg;
        unsigned a[2][4];
        #pragma unroll
        for (int mf = 0; mf < 2; mf++) {
            const __nv_bfloat16* ar = g_hidb + (size_t)(m0 + mf*16 + g)*256 + k;
            a[mf][0] = *(const unsigned*)ar;
            a[mf][1] = *(const unsigned*)(ar + 8*256);
            a[mf][2] = *(const unsigned*)(ar + 8);
            a[mf][3] = *(const unsigned*)(ar + 8*256 + 8);
        }
        #pragma unroll
        for (int nf = 0; nf < 8; nf++) {
            const __nv_bfloat16* br = w2s + (nf*8 + g)*264 + k;
            unsigned b0 = *(const unsigned*)br;
            unsigned bq = *(const unsigned*)(br + 8);
            #pragma unroll
            for (int mf = 0; mf < 2; mf++)
                mma16816(c[mf][nf][0], c[mf][nf][1], c[mf][nf][2], c[mf][nf][3],
                         a[mf][0], a[mf][1], a[mf][2], a[mf][3], b0, bq);
        }
    }

    #pragma unroll
    for (int mf = 0; mf < 2; mf++) {
        const int r = m0 + mf*16 + g;
        #pragma unroll
        for (int nf = 0; nf < 8; nf++) {
            int e = nf*8 + 2*tg;
            float2 o0 = *(float2*)&out[(size_t)r*64 + e];
            float2 o1 = *(float2*)&out[(size_t)(r+8)*64 + e];
            o0.x += b2s[e]   + c[mf][nf][0];
            o0.y += b2s[e+1] + c[mf][nf][1];
            o1.x += b2s[e]   + c[mf][nf][2];
            o1.y += b2s[e+1] + c[mf][nf][3];
            *(float2*)&out[(size_t)r*64 + e]     = o0;
            *(float2*)&out[(size_t)(r+8)*64 + e] = o1;
        }
    }
}

// ============ launch ============
extern "C" void kernel_launch(void* const* d_in, const int* in_sizes, int n_in,
                              void* d_out, int out_size)
{
    const float* x     = (const float*)d_in[0];
    const float* maddr = (const float*)d_in[1];
    const float* mvals = (const float*)d_in[2];
    const float* anw   = (const float*)d_in[3];
    const float* wq    = (const float*)d_in[4];
    const float* wk    = (const float*)d_in[5];
    const float* wv    = (const float*)d_in[6];
    const float* wo    = (const float*)d_in[7];
    const float* mnw   = (const float*)d_in[8];
    const float* mq    = (const float*)d_in[9];
    const float* mo    = (const float*)d_in[10];
    const float* fnw   = (const float*)d_in[11];
    const float* w1    = (const float*)d_in[12];
    const float* b1    = (const float*)d_in[13];
    const float* w2    = (const float*)d_in[14];
    const float* b2    = (const float*)d_in[15];
    float* out = (float*)d_out;

    const int QKV_SMEM  = (3*4224 + 64) * 4 + 8*128*8;            // 59,136
    const int ATT_SMEM  = 32768 + 33024 + 4096;                   // 69,888
    const int MEM1_SMEM = 64*72*2;                                // 9,216
    const int MEM2_SMEM = (2112 + 2080 + 64 + 8*96) * 4;          // 20,096
    const int FFN1_SMEM = 36864 + 18432 + 9216 + 34816 + (256 + 64)*4; // 100,608
    const int FFN2_SMEM = 64*264*2 + 64*4;                        // 34,048

    cudaFuncSetAttribute(qkv_kernel, cudaFuncAttributeMaxDynamicSharedMemorySize, QKV_SMEM);
    cudaFuncSetAttribute(attn_kernel, cudaFuncAttributeMaxDynamicSharedMemorySize, ATT_SMEM);
    cudaFuncSetAttribute(mem1_kernel, cudaFuncAttributeMaxDynamicSharedMemorySize, MEM1_SMEM);
    cudaFuncSetAttribute(mem2_kernel, cudaFuncAttributeMaxDynamicSharedMemorySize, MEM2_SMEM);
    cudaFuncSetAttribute(ffn1_kernel, cudaFuncAttributeMaxDynamicSharedMemorySize, FFN1_SMEM);
    cudaFuncSetAttribute(ffn2_kernel, cudaFuncAttributeMaxDynamicSharedMemorySize, FFN2_SMEM);

    qkv_kernel<<<296, 256, QKV_SMEM>>>(x, anw, wq, wk, wv);
    attn_kernel<<<1024, 128, ATT_SMEM>>>();
    mem1_kernel<<<256, 256, MEM1_SMEM>>>(x, wo, out);
    mem2_kernel<<<592, 256, MEM2_SMEM>>>(mvals, maddr, mnw, mq, out);
    ffn1_kernel<<<256, 256, FFN1_SMEM>>>(fnw, b1, mo, w1, out);
    ffn2_kernel<<<256, 128, FFN2_SMEM>>>(b2, w2, out);
}

// round 15
// speedup vs baseline: 1.0527x; 1.0527x over previous
#include <cuda_runtime.h>
#include <cuda_bf16.h>
#include <math.h>

#define B_  32
#define S_  1024
#define E_  64
#define H_  4
#define HD_ 16
#define HID_ 256
#define AD_ 32
#define NS_ 64
#define NT_ (B_*S_)
#define QSCALE (0.25f * 1.4426950408889634f)

__device__ __align__(16) __nv_bfloat16 g_qh[B_*H_*S_*HD_];
__device__ __align__(16) __nv_bfloat16 g_kh[B_*H_*S_*HD_];
__device__ __align__(16) __nv_bfloat16 g_vt[B_*H_*HD_*S_];
__device__ __align__(16) __nv_bfloat16 g_ob[(size_t)NT_*E_];      // attn out, bf16
__device__ __align__(16) __nv_bfloat16 g_rv[(size_t)NT_*E_];      // read_vals bf16
__device__ __align__(16) __nv_bfloat16 g_hidb[(size_t)NT_*HID_];
__device__ __align__(16) __nv_bfloat16 g_w1b[HID_*E_];
__device__ __align__(16) __nv_bfloat16 g_w2b[E_*HID_];
__device__ __align__(16) __nv_bfloat16 g_wob[E_*E_];
__device__ __align__(16) __nv_bfloat16 g_mob[E_*E_];

__device__ __forceinline__ unsigned long long pk2(float lo, float hi) {
    unsigned long long r; asm("mov.b64 %0,{%1,%2};" : "=l"(r) : "f"(lo), "f"(hi)); return r;
}
__device__ __forceinline__ float2 upk2(unsigned long long v) {
    float2 f; asm("mov.b64 {%0,%1},%2;" : "=f"(f.x), "=f"(f.y) : "l"(v)); return f;
}
__device__ __forceinline__ unsigned long long ffma2_(unsigned long long a,
    unsigned long long b, unsigned long long c) {
    unsigned long long d;
    asm("fma.rn.f32x2 %0,%1,%2,%3;" : "=l"(d) : "l"(a), "l"(b), "l"(c)); return d;
}
__device__ __forceinline__ float ex2_(float x) {
    float y; asm("ex2.approx.f32 %0,%1;" : "=f"(y) : "f"(x)); return y;
}
__device__ __forceinline__ float gelu_(float v) {
    float u = v * (0.7978845608f + 0.0356774081f * v * v);
    float e = ex2_(u * 2.885390082f);
    float r; asm("rcp.approx.f32 %0,%1;" : "=f"(r) : "f"(1.f + e));
    return 0.5f * v * (2.f - 2.f*r);
}
__device__ __forceinline__ unsigned pbf_(float lo, float hi) {
    unsigned r; asm("cvt.rn.bf16x2.f32 %0,%1,%2;" : "=r"(r) : "f"(hi), "f"(lo)); return r;
}
__device__ __forceinline__ void mma16816(float& c0, float& c1, float& c2, float& c3,
    unsigned a0, unsigned a1, unsigned a2, unsigned a3, unsigned b0, unsigned b1) {
    asm volatile("mma.sync.aligned.m16n8k16.row.col.f32.bf16.bf16.f32 "
        "{%0,%1,%2,%3},{%4,%5,%6,%7},{%8,%9},{%0,%1,%2,%3};"
        : "+f"(c0), "+f"(c1), "+f"(c2), "+f"(c3)
        : "r"(a0), "r"(a1), "r"(a2), "r"(a3), "r"(b0), "r"(b1));
}

// ============ kernel 0: pre-convert weights to bf16 ============
__global__ void __launch_bounds__(256) cvt_kernel(
    const float* __restrict__ w1, const float* __restrict__ w2,
    const float* __restrict__ wo, const float* __restrict__ mo)
{
    int i = blockIdx.x*256 + threadIdx.x;
    if (i < HID_*E_) {
        g_w1b[i] = __float2bfloat16(w1[i]);
        g_w2b[i] = __float2bfloat16(w2[i]);
    }
    if (i < E_*E_) {
        g_wob[i] = __float2bfloat16(wo[i]);
        g_mob[i] = __float2bfloat16(mo[i]);
    }
}

// ============ kernel 1: rmsnorm + QKV (bf16 out, V transposed) ============
__global__ void __launch_bounds__(256) qkv_kernel(
    const float* __restrict__ x, const float* __restrict__ nw,
    const float* __restrict__ wq, const float* __restrict__ wk,
    const float* __restrict__ wv)
{
    extern __shared__ float sm[];
    float* ws  = sm;                 // 3*64*66
    float* nws = ws + 3*4224;
    unsigned long long* htp_all = (unsigned long long*)(nws + 64);

    const int tid = threadIdx.x, lane = tid & 31, w = tid >> 5;

    for (int i = tid; i < 64*64; i += blockDim.x) {
        int e = i >> 6, j = i & 63;
        ws[0*4224 + e*66 + j] = wq[i];
        ws[1*4224 + e*66 + j] = wk[i];
        ws[2*4224 + e*66 + j] = wv[i];
    }
    if (tid < 64) nws[tid] = nw[tid];
    __syncthreads();

    unsigned long long* htp = htp_all + w*128;
    float* hview = (float*)htp;

    for (int chunk = blockIdx.x*8 + w; chunk < NT_/4; chunk += gridDim.x*8) {
        const int tok0 = chunk*4;
        #pragma unroll
        for (int t = 0; t < 4; t++) {
            float xa = x[(tok0+t)*64 + lane];
            float xb = x[(tok0+t)*64 + lane + 32];
            float ss = xa*xa + xb*xb;
            #pragma unroll
            for (int o = 16; o; o >>= 1) ss += __shfl_xor_sync(~0u, ss, o);
            float rinv = rsqrtf(ss * (1.f/64.f) + 1e-5f);
            int tp = t >> 1, c = t & 1;
            hview[(tp*64 + lane)*2 + c]      = xa * rinv * nws[lane];
            hview[(tp*64 + lane + 32)*2 + c] = xb * rinv * nws[lane + 32];
        }
        __syncwarp();

        unsigned long long acc[3][2][2];
        #pragma unroll
        for (int p = 0; p < 3; p++)
            #pragma unroll
            for (int r = 0; r < 2; r++) { acc[p][r][0] = 0ull; acc[p][r][1] = 0ull; }

        #pragma unroll 4
        for (int j = 0; j < 64; j += 2) {
            ulonglong2 h0 = *(const ulonglong2*)(htp + j);
            ulonglong2 h1 = *(const ulonglong2*)(htp + 64 + j);
            #pragma unroll
            for (int p = 0; p < 3; p++)
                #pragma unroll
                for (int r = 0; r < 2; r++) {
                    float2 wf = *(const float2*)(ws + p*4224 + (lane + r*32)*66 + j);
                    unsigned long long wx = pk2(wf.x, wf.x);
                    unsigned long long wy = pk2(wf.y, wf.y);
                    acc[p][r][0] = ffma2_(wx, h0.x, acc[p][r][0]);
                    acc[p][r][0] = ffma2_(wy, h0.y, acc[p][r][0]);
                    acc[p][r][1] = ffma2_(wx, h1.x, acc[p][r][1]);
                    acc[p][r][1] = ffma2_(wy, h1.y, acc[p][r][1]);
                }
        }

        const int b0 = tok0 >> 10, s0 = tok0 & 1023;
        #pragma unroll
        for (int r = 0; r < 2; r++) {
            int e = lane + r*32, hh = e >> 4, d = e & 15;
            size_t bhi = (size_t)(b0*H_ + hh);
            #pragma unroll
            for (int tp = 0; tp < 2; tp++) {
                int s = s0 + tp*2;
                float2 vq = upk2(acc[0][r][tp]);
                g_qh[(bhi*S_ + s  )*16 + d] = __float2bfloat16(vq.x * QSCALE);
                g_qh[(bhi*S_ + s+1)*16 + d] = __float2bfloat16(vq.y * QSCALE);
                float2 vk = upk2(acc[1][r][tp]);
                g_kh[(bhi*S_ + s  )*16 + d] = __float2bfloat16(vk.x);
                g_kh[(bhi*S_ + s+1)*16 + d] = __float2bfloat16(vk.y);
                float2 vv = upk2(acc[2][r][tp]);
                *(unsigned*)&g_vt[(bhi*16 + d)*S_ + s] = pbf_(vv.x, vv.y);
            }
        }
        __syncwarp();
    }
}

// ============ kernel 2: causal attention via bf16 HMMA (bf16 output) ============
__global__ void __launch_bounds__(128, 3) attn_kernel()
{
    const int bidx = blockIdx.x;
    const int qt = 7 - (bidx >> 7);          // heavy tiles first
    const int bh = bidx & 127;
    const int nk = (qt + 1) * 128;
    const int qbase = qt * 128;

    extern __shared__ char smc[];
    __nv_bfloat16* Ks = (__nv_bfloat16*)smc;                    // [nk][16]
    __nv_bfloat16* Vt = (__nv_bfloat16*)(smc + 32768);          // [16][1032]
    __nv_bfloat16* Qs = (__nv_bfloat16*)(smc + 32768 + 33024);  // [128][16]

    const int tid = threadIdx.x, lane = tid & 31, w = tid >> 5;

    {
        const uint4* src = (const uint4*)(g_kh + (size_t)bh * S_ * 16);
        uint4* dst = (uint4*)Ks;
        for (int i = tid; i < nk*2; i += 128) dst[i] = src[i];
    }
    {
        const uint4* src = (const uint4*)(g_qh + ((size_t)bh * S_ + qbase) * 16);
        uint4* dst = (uint4*)Qs;
        dst[tid] = src[tid];
        dst[tid + 128] = src[tid + 128];
    }
    for (int d = w; d < 16; d += 4) {
        const uint4* src = (const uint4*)(g_vt + ((size_t)bh*16 + d) * S_);
        uint4* dst = (uint4*)(Vt + d * 1032);
        for (int i = lane; i < nk/8; i += 32) dst[i] = src[i];
    }
    __syncthreads();

    const int g = lane >> 2, tg = lane & 3;

    unsigned qa[2][4];
    #pragma unroll
    for (int mf = 0; mf < 2; mf++) {
        int rr = w*32 + mf*16 + g;
        qa[mf][0] = *(const unsigned*)&Qs[ rr     *16 + 2*tg    ];
        qa[mf][1] = *(const unsigned*)&Qs[(rr + 8)*16 + 2*tg    ];
        qa[mf][2] = *(const unsigned*)&Qs[ rr     *16 + 2*tg + 8];
        qa[mf][3] = *(const unsigned*)&Qs[(rr + 8)*16 + 2*tg + 8];
    }

    float o[2][2][4];
    #pragma unroll
    for (int mf = 0; mf < 2; mf++)
        #pragma unroll
        for (int dh = 0; dh < 2; dh++)
            o[mf][dh][0] = o[mf][dh][1] = o[mf][dh][2] = o[mf][dh][3] = 0.f;
    float lsum[2][2] = {{0.f,0.f},{0.f,0.f}};

    auto step = [&](int j0, bool MASK) {
        unsigned kb[2][2], vb[2][2];
        #pragma unroll
        for (int kh = 0; kh < 2; kh++) {
            const __nv_bfloat16* kr = Ks + (j0 + kh*8 + g)*16 + 2*tg;
            kb[kh][0] = *(const unsigned*)kr;
            kb[kh][1] = *(const unsigned*)(kr + 8);
        }
        #pragma unroll
        for (int dh = 0; dh < 2; dh++) {
            const __nv_bfloat16* vr = Vt + (dh*8 + g)*1032 + j0 + 2*tg;
            vb[dh][0] = *(const unsigned*)vr;
            vb[dh][1] = *(const unsigned*)(vr + 8);
        }
        #pragma unroll
        for (int mf = 0; mf < 2; mf++) {
            float c[2][4];
            #pragma unroll
            for (int kh = 0; kh < 2; kh++) {
                c[kh][0] = c[kh][1] = c[kh][2] = c[kh][3] = 0.f;
                mma16816(c[kh][0], c[kh][1], c[kh][2], c[kh][3],
                         qa[mf][0], qa[mf][1], qa[mf][2], qa[mf][3],
                         kb[kh][0], kb[kh][1]);
            }
            const int r0 = qbase + w*32 + mf*16 + g, r1 = r0 + 8;
            float p[2][4];
            #pragma unroll
            for (int kh = 0; kh < 2; kh++) {
                int k0 = j0 + kh*8 + 2*tg;
                p[kh][0] = (!MASK || k0     <= r0) ? ex2_(c[kh][0]) : 0.f;
                p[kh][1] = (!MASK || k0 + 1 <= r0) ? ex2_(c[kh][1]) : 0.f;
                p[kh][2] = (!MASK || k0     <= r1) ? ex2_(c[kh][2]) : 0.f;
                p[kh][3] = (!MASK || k0 + 1 <= r1) ? ex2_(c[kh][3]) : 0.f;
            }
            lsum[mf][0] += (p[0][0] + p[0][1]) + (p[1][0] + p[1][1]);
            lsum[mf][1] += (p[0][2] + p[0][3]) + (p[1][2] + p[1][3]);
            unsigned pa0 = pbf_(p[0][0], p[0][1]);
            unsigned pa1 = pbf_(p[0][2], p[0][3]);
            unsigned pa2 = pbf_(p[1][0], p[1][1]);
            unsigned pa3 = pbf_(p[1][2], p[1][3]);
            #pragma unroll
            for (int dh = 0; dh < 2; dh++)
                mma16816(o[mf][dh][0], o[mf][dh][1], o[mf][dh][2], o[mf][dh][3],
                         pa0, pa1, pa2, pa3, vb[dh][0], vb[dh][1]);
        }
    };

    for (int j0 = 0; j0 < qbase; j0 += 16) step(j0, false);
    const int wlast = qbase + w*32 + 31;
    for (int j0 = qbase; j0 < nk; j0 += 16) {
        if (j0 > wlast) break;
        step(j0, true);
    }

    const int b = bh >> 2, h = bh & 3;
    #pragma unroll
    for (int mf = 0; mf < 2; mf++) {
        float l0 = lsum[mf][0], l1 = lsum[mf][1];
        l0 += __shfl_xor_sync(~0u, l0, 1); l0 += __shfl_xor_sync(~0u, l0, 2);
        l1 += __shfl_xor_sync(~0u, l1, 1); l1 += __shfl_xor_sync(~0u, l1, 2);
        float i0 = 1.f / l0, i1 = 1.f / l1;
        int r0 = qbase + w*32 + mf*16 + g;
        __nv_bfloat16* b0p = g_ob + (size_t)(b*S_ + r0)*64 + h*16;
        __nv_bfloat16* b1p = b0p + 8*64;
        *(unsigned*)(b0p + 2*tg)     = pbf_(o[mf][0][0]*i0, o[mf][0][1]*i0);
        *(unsigned*)(b0p + 8 + 2*tg) = pbf_(o[mf][1][0]*i0, o[mf][1][1]*i0);
        *(unsigned*)(b1p + 2*tg)     = pbf_(o[mf][0][2]*i1, o[mf][0][3]*i1);
        *(unsigned*)(b1p + 8 + 2*tg) = pbf_(o[mf][1][2]*i1, o[mf][1][3]*i1);
    }
}

// ============ kernel 3a: x1 = x + av@wo^T  (HMMA, 16 tok/warp) ============
__global__ void __launch_bounds__(256) mem1_kernel(
    const float* __restrict__ x, float* __restrict__ out)
{
    extern __shared__ char smc[];
    __nv_bfloat16* woB = (__nv_bfloat16*)smc;   // [64][72]

    const int tid = threadIdx.x, lane = tid & 31, w = tid >> 5;
    const int g = lane >> 2, tg = lane & 3;
    const int m0 = blockIdx.x*128 + w*16;

    for (int i = tid; i < 2048; i += 256) {
        int o = i >> 5, j = (i & 31)*2;
        *(unsigned*)&woB[o*72 + j] = ((const unsigned*)g_wob)[i];
    }
    __syncthreads();

    float c[8][4];
    #pragma unroll
    for (int nf = 0; nf < 8; nf++)
        c[nf][0] = c[nf][1] = c[nf][2] = c[nf][3] = 0.f;

    #pragma unroll
    for (int ks = 0; ks < 4; ks++) {
        const int k = ks*16 + 2*tg;
        const __nv_bfloat16* ar = g_ob + (size_t)(m0 + g)*64 + k;
        unsigned a0 = *(const unsigned*)ar;
        unsigned a1 = *(const unsigned*)(ar + 8*64);
        unsigned a2 = *(const unsigned*)(ar + 8);
        unsigned a3 = *(const unsigned*)(ar + 8*64 + 8);
        #pragma unroll
        for (int nf = 0; nf < 8; nf++) {
            const __nv_bfloat16* br = woB + (nf*8 + g)*72 + k;
            mma16816(c[nf][0], c[nf][1], c[nf][2], c[nf][3],
                     a0, a1, a2, a3,
                     *(const unsigned*)br, *(const unsigned*)(br + 8));
        }
    }

    const int r = m0 + g;
    #pragma unroll
    for (int nf = 0; nf < 8; nf++) {
        int e = nf*8 + 2*tg;
        float2 x0 = *(const float2*)&x[(size_t)r*64 + e];
        float2 x1 = *(const float2*)&x[(size_t)(r+8)*64 + e];
        *(float2*)&out[(size_t)r*64 + e] =
            make_float2(x0.x + c[nf][0], x0.y + c[nf][1]);
        *(float2*)&out[(size_t)(r+8)*64 + e] =
            make_float2(x1.x + c[nf][2], x1.y + c[nf][3]);
    }
}

// ============ kernel 3b: fp32 middle, token-pair f32x2 packed ============
// warp = 2 tokens per iteration; matvecs packed, selection exact per token.
__global__ void __launch_bounds__(256) mem2_kernel(
    const float* __restrict__ mvals, const float* __restrict__ maddr,
    const float* __restrict__ mnw,   const float* __restrict__ mq,
    const float* __restrict__ out)
{
    extern __shared__ float sm[];
    float* mqT  = sm;              // [64][33]
    float* aT   = mqT + 2112;      // [32][65]
    float* mnws = aT + 2080;       // 64
    unsigned long long* u64base = (unsigned long long*)(mnws + 64);  // 8w * 96

    const int tid = threadIdx.x, lane = tid & 31, w = tid >> 5;

    for (int i = tid; i < AD_*E_; i += blockDim.x) {
        int a = i >> 6, e = i & 63;
        mqT[e*33 + a] = mq[i];
    }
    if (tid < 64) mnws[tid] = mnw[tid];
    if (tid < 64) {
        float ssum = 0.f, v[32];
        #pragma unroll
        for (int a = 0; a < 32; a++) { v[a] = maddr[tid*32 + a]; ssum += v[a]*v[a]; }
        float rn = 1.f / fmaxf(sqrtf(ssum), 1e-12f);
        #pragma unroll
        for (int a = 0; a < 32; a++) aT[a*65 + tid] = v[a] * rn;
    }
    __syncthreads();

    unsigned long long* hp = u64base + w*96;   // 64 u64
    unsigned long long* qp = hp + 64;          // 32 u64

    for (int pr = blockIdx.x*8 + w; pr < NT_/2; pr += gridDim.x*8) {
        const int tok0 = pr*2, tok1 = tok0 + 1;
        // rmsnorm both tokens (interleaved reduce chains)
        float a0 = out[(size_t)tok0*64 + lane];
        float b0 = out[(size_t)tok0*64 + lane + 32];
        float a1 = out[(size_t)tok1*64 + lane];
        float b1 = out[(size_t)tok1*64 + lane + 32];
        float ss0 = a0*a0 + b0*b0, ss1 = a1*a1 + b1*b1;
        #pragma unroll
        for (int o = 16; o; o >>= 1) {
            ss0 += __shfl_xor_sync(~0u, ss0, o);
            ss1 += __shfl_xor_sync(~0u, ss1, o);
        }
        float ri0 = rsqrtf(ss0 * (1.f/64.f) + 1e-5f);
        float ri1 = rsqrtf(ss1 * (1.f/64.f) + 1e-5f);
        float w0 = mnws[lane], w1 = mnws[lane + 32];
        hp[lane]      = pk2(a0*ri0*w0, a1*ri1*w0);
        hp[lane + 32] = pk2(b0*ri0*w1, b1*ri1*w1);
        __syncwarp();

        // mq-proj packed: q[lane] for both tokens
        unsigned long long qacc = 0ull;
        #pragma unroll 8
        for (int e = 0; e < 64; e++) {
            float mw = mqT[e*33 + lane];
            qacc = ffma2_(pk2(mw, mw), hp[e], qacc);
        }
        float2 qf = upk2(qacc);
        float qs0 = qf.x*qf.x, qs1 = qf.y*qf.y;
        #pragma unroll
        for (int o = 16; o; o >>= 1) {
            qs0 += __shfl_xor_sync(~0u, qs0, o);
            qs1 += __shfl_xor_sync(~0u, qs1, o);
        }
        float rq0 = 1.f / fmaxf(sqrtf(qs0), 1e-12f);
        float rq1 = 1.f / fmaxf(sqrtf(qs1), 1e-12f);
        qp[lane] = pk2(qf.x*rq0, qf.y*rq1);
        __syncwarp();

        // scores packed
        unsigned long long s0acc = 0ull, s1acc = 0ull;
        #pragma unroll 8
        for (int a = 0; a < 32; a++) {
            unsigned long long qv = qp[a];
            float wa = aT[a*65 + lane], wb = aT[a*65 + lane + 32];
            s0acc = ffma2_(pk2(wa, wa), qv, s0acc);
            s1acc = ffma2_(pk2(wb, wb), qv, s1acc);
        }
        float2 s0f = upk2(s0acc), s1f = upk2(s1acc);

        // exact per-token selection + gather
        #pragma unroll
        for (int t = 0; t < 2; t++) {
            const int tok = tok0 + t;
            const int b = tok >> 10;
            float sc0 = (t == 0 ? s0f.x : s0f.y) * 4.f;
            float sc1 = (t == 0 ? s1f.x : s1f.y) * 4.f;
            unsigned f0 = __float_as_uint(sc0);
            unsigned m0 = (f0 & 0x80000000u) ? ~f0 : (f0 | 0x80000000u);
            unsigned key0 = (m0 & 0xFFFFFFC0u) | (unsigned)(63 - lane);
            unsigned f1 = __float_as_uint(sc1);
            unsigned m1 = (f1 & 0x80000000u) ? ~f1 : (f1 | 0x80000000u);
            unsigned key1 = (m1 & 0xFFFFFFC0u) | (unsigned)(31 - lane);
            float tv[8]; int ti[8];
            #pragma unroll
            for (int k = 0; k < 8; k++) {
                unsigned loc = key0 > key1 ? key0 : key1;
                unsigned r = __reduce_max_sync(0xffffffffu, loc);
                int idx = 63 - (int)(r & 63u);
                float vsel = __shfl_sync(0xffffffffu, (idx >= 32) ? sc1 : sc0, idx & 31);
                tv[k] = vsel; ti[k] = idx;
                if (idx == lane)      key0 = 0u;
                if (idx == lane + 32) key1 = 0u;
            }
            float wsum = 0.f, wk8[8];
            #pragma unroll
            for (int k = 0; k < 8; k++) { wk8[k] = __expf(tv[k] - tv[0]); wsum += wk8[k]; }
            float winv = 1.f / wsum;
            const float* mb = mvals + b * NS_ * E_;
            float r0 = 0.f, r1 = 0.f;
            #pragma unroll
            for (int k = 0; k < 8; k++) {
                float wv = wk8[k] * winv;
                const float* mrow = mb + ti[k]*64;
                r0 += wv * mrow[lane];
                r1 += wv * mrow[lane + 32];
            }
            g_rv[(size_t)tok*64 + lane]      = __float2bfloat16(r0);
            g_rv[(size_t)tok*64 + lane + 32] = __float2bfloat16(r1);
        }
    }
}

// ============ kernel 3c: out += rv@mo^T  (HMMA) ============
__global__ void __launch_bounds__(128, 4) mem3_kernel(float* __restrict__ out)
{
    extern __shared__ char smc[];
    __nv_bfloat16* moB = (__nv_bfloat16*)smc;   // [64][72]

    const int tid = threadIdx.x, lane = tid & 31, w = tid >> 5;
    const int g = lane >> 2, tg = lane & 3;
    const int m0 = blockIdx.x*128 + w*32;

    for (int i = tid; i < 2048; i += 128) {
        int o = i >> 5, j = (i & 31)*2;
        *(unsigned*)&moB[o*72 + j] = ((const unsigned*)g_mob)[i];
    }
    __syncthreads();

    float c[2][8][4];
    #pragma unroll
    for (int mf = 0; mf < 2; mf++)
        #pragma unroll
        for (int nf = 0; nf < 8; nf++)
            c[mf][nf][0] = c[mf][nf][1] = c[mf][nf][2] = c[mf][nf][3] = 0.f;

    #pragma unroll
    for (int ks = 0; ks < 4; ks++) {
        const int k = ks*16 + 2*tg;
        unsigned a[2][4];
        #pragma unroll
        for (int mf = 0; mf < 2; mf++) {
            const __nv_bfloat16* ar = g_rv + (size_t)(m0 + mf*16 + g)*64 + k;
            a[mf][0] = *(const unsigned*)ar;
            a[mf][1] = *(const unsigned*)(ar + 8*64);
            a[mf][2] = *(const unsigned*)(ar + 8);
            a[mf][3] = *(const unsigned*)(ar + 8*64 + 8);
        }
        #pragma unroll
        for (int nf = 0; nf < 8; nf++) {
            const __nv_bfloat16* br = moB + (nf*8 + g)*72 + k;
            unsigned b0 = *(const unsigned*)br;
            unsigned bq = *(const unsigned*)(br + 8);
            #pragma unroll
            for (int mf = 0; mf < 2; mf++)
                mma16816(c[mf][nf][0], c[mf][nf][1], c[mf][nf][2], c[mf][nf][3],
                         a[mf][0], a[mf][1], a[mf][2], a[mf][3], b0, bq);
        }
    }

    #pragma unroll
    for (int mf = 0; mf < 2; mf++) {
        const int r = m0 + mf*16 + g;
        #pragma unroll
        for (int nf = 0; nf < 8; nf++) {
            int e = nf*8 + 2*tg;
            float2 o0 = *(float2*)&out[(size_t)r*64 + e];
            float2 o1 = *(float2*)&out[(size_t)(r+8)*64 + e];
            o0.x += c[mf][nf][0]; o0.y += c[mf][nf][1];
            o1.x += c[mf][nf][2]; o1.y += c[mf][nf][3];
            *(float2*)&out[(size_t)r*64 + e]     = o0;
            *(float2*)&out[(size_t)(r+8)*64 + e] = o1;
        }
    }
}

// ============ kernel 4a: FFN GEMM1 via HMMA + fast GELU -> g_hidb ============
__global__ void __launch_bounds__(256, 2) ffn1_kernel(
    const float* __restrict__ fnw, const float* __restrict__ b1,
    const float* __restrict__ out)
{
    extern __shared__ char smc[];
    __nv_bfloat16* w1s = (__nv_bfloat16*)smc;            // [256][72]
    __nv_bfloat16* As  = (__nv_bfloat16*)(smc + 36864);  // [128][72]
    float* b1s = (float*)(smc + 36864 + 18432);          // 256
    float* fns = b1s + 256;                              // 64

    const int tid = threadIdx.x, lane = tid & 31, w = tid >> 5;
    const int g = lane >> 2, tg = lane & 3;
    const int wm = w & 3, nh = w >> 2;
    const int tok0 = blockIdx.x * 128;

    for (int i = tid; i < 256*32; i += 256) {
        int j2 = i*2;
        int o = j2 >> 6, j = j2 & 63;
        *(unsigned*)&w1s[o*72 + j] = ((const unsigned*)g_w1b)[i];
    }
    b1s[tid] = b1[tid];
    if (tid < 64) fns[tid] = fnw[tid];
    __syncthreads();

    if (tid < 128) {
        const float4* xr = (const float4*)(out + (size_t)(tok0 + tid)*64);
        float4 v[16];
        float ss = 0.f;
        #pragma unroll
        for (int i = 0; i < 16; i++) {
            v[i] = xr[i];
            ss += v[i].x*v[i].x + v[i].y*v[i].y + v[i].z*v[i].z + v[i].w*v[i].w;
        }
        float rinv = rsqrtf(ss * (1.f/64.f) + 1e-5f);
        #pragma unroll
        for (int i = 0; i < 16; i++) {
            *(unsigned*)&As[tid*72 + 4*i]     = pbf_(v[i].x*rinv*fns[4*i],   v[i].y*rinv*fns[4*i+1]);
            *(unsigned*)&As[tid*72 + 4*i + 2] = pbf_(v[i].z*rinv*fns[4*i+2], v[i].w*rinv*fns[4*i+3]);
        }
    }
    __syncthreads();

    unsigned a[4][2][4];
    #pragma unroll
    for (int ks = 0; ks < 4; ks++)
        #pragma unroll
        for (int mf = 0; mf < 2; mf++) {
            int r = wm*32 + mf*16 + g;
            int k = ks*16 + 2*tg;
            a[ks][mf][0] = *(const unsigned*)&As[ r      *72 + k];
            a[ks][mf][1] = *(const unsigned*)&As[(r + 8) *72 + k];
            a[ks][mf][2] = *(const unsigned*)&As[ r      *72 + k + 8];
            a[ks][mf][3] = *(const unsigned*)&As[(r + 8) *72 + k + 8];
        }

    #pragma unroll
    for (int ch = 0; ch < 2; ch++) {
        const int n0 = nh*128 + ch*64;
        float c[2][8][4];
        #pragma unroll
        for (int mf = 0; mf < 2; mf++)
            #pragma unroll
            for (int nf = 0; nf < 8; nf++)
                c[mf][nf][0] = c[mf][nf][1] = c[mf][nf][2] = c[mf][nf][3] = 0.f;

        #pragma unroll
        for (int ks = 0; ks < 4; ks++) {
            #pragma unroll
            for (int nf = 0; nf < 8; nf++) {
                const __nv_bfloat16* br = w1s + (n0 + nf*8 + g)*72 + ks*16 + 2*tg;
                unsigned b0 = *(const unsigned*)br;
                unsigned bq = *(const unsigned*)(br + 8);
                #pragma unroll
                for (int mf = 0; mf < 2; mf++)
                    mma16816(c[mf][nf][0], c[mf][nf][1], c[mf][nf][2], c[mf][nf][3],
                             a[ks][mf][0], a[ks][mf][1], a[ks][mf][2], a[ks][mf][3],
                             b0, bq);
            }
        }

        #pragma unroll
        for (int mf = 0; mf < 2; mf++) {
            const int r = tok0 + wm*32 + mf*16 + g;
            #pragma unroll
            for (int nf = 0; nf < 8; nf++) {
                int e = n0 + nf*8 + 2*tg;
                float be0 = b1s[e], be1 = b1s[e+1];
                *(unsigned*)&g_hidb[(size_t)r*256 + e] =
                    pbf_(gelu_(c[mf][nf][0] + be0), gelu_(c[mf][nf][1] + be1));
                *(unsigned*)&g_hidb[(size_t)(r+8)*256 + e] =
                    pbf_(gelu_(c[mf][nf][2] + be0), gelu_(c[mf][nf][3] + be1));
            }
        }
    }
}

// ============ kernel 4b: FFN GEMM2 via HMMA + residual ============
__global__ void __launch_bounds__(128, 4) ffn2_kernel(
    const float* __restrict__ b2, float* __restrict__ out)
{
    extern __shared__ char smc[];
    __nv_bfloat16* w2s = (__nv_bfloat16*)smc;   // [64][264]
    float* b2s = (float*)(smc + 64*264*2);

    const int tid = threadIdx.x, lane = tid & 31, w = tid >> 5;
    const int g = lane >> 2, tg = lane & 3;
    const int tok0 = blockIdx.x * 128;

    for (int i = tid; i < 64*128; i += 128) {
        int j2 = i*2;
        int e = j2 >> 8, o = j2 & 255;
        *(unsigned*)&w2s[e*264 + o] = ((const unsigned*)g_w2b)[i];
    }
    if (tid < 64) b2s[tid] = b2[tid];
    __syncthreads();

    float c[2][8][4];
    #pragma unroll
    for (int mf = 0; mf < 2; mf++)
        #pragma unroll
        for (int nf = 0; nf < 8; nf++)
            c[mf][nf][0] = c[mf][nf][1] = c[mf][nf][2] = c[mf][nf][3] = 0.f;

    const int m0 = tok0 + w*32;
    #pragma unroll 4
    for (int ks = 0; ks < 16; ks++) {
        const int k = ks*16 + 2*tg;
        unsigned a[2][4];
        #pragma unroll
        for (int mf = 0; mf < 2; mf++) {
            const __nv_bfloat16* ar = g_hidb + (size_t)(m0 + mf*16 + g)*256 + k;
            a[mf][0] = *(const unsigned*)ar;
            a[mf][1] = *(const unsigned*)(ar + 8*256);
            a[mf][2] = *(const unsigned*)(ar + 8);
            a[mf][3] = *(const unsigned*)(ar + 8*256 + 8);
        }
        #pragma unroll
        for (int nf = 0; nf < 8; nf++) {
            const __nv_bfloat16* br = w2s + (nf*8 + g)*264 + k;
            unsigned b0 = *(const unsigned*)br;
            unsigned bq = *(const unsigned*)(br + 8);
            #pragma unroll
            for (int mf = 0; mf < 2; mf++)
                mma16816(c[mf][nf][0], c[mf][nf][1], c[mf][nf][2], c[mf][nf][3],
                         a[mf][0], a[mf][1], a[mf][2], a[mf][3], b0, bq);
        }
    }

    #pragma unroll
    for (int mf = 0; mf < 2; mf++) {
        const int r = m0 + mf*16 + g;
        #pragma unroll
        for (int nf = 0; nf < 8; nf++) {
            int e = nf*8 + 2*tg;
            float2 o0 = *(float2*)&out[(size_t)r*64 + e];
            float2 o1 = *(float2*)&out[(size_t)(r+8)*64 + e];
            o0.x += b2s[e]   + c[mf][nf][0];
            o0.y += b2s[e+1] + c[mf][nf][1];
            o1.x += b2s[e]   + c[mf][nf][2];
            o1.y += b2s[e+1] + c[mf][nf][3];
            *(float2*)&out[(size_t)r*64 + e]     = o0;
            *(float2*)&out[(size_t)(r+8)*64 + e] = o1;
        }
    }
}

// ============ launch ============
extern "C" void kernel_launch(void* const* d_in, const int* in_sizes, int n_in,
                              void* d_out, int out_size)
{
    const float* x     = (const float*)d_in[0];
    const float* maddr = (const float*)d_in[1];
    const float* mvals = (const float*)d_in[2];
    const float* anw   = (const float*)d_in[3];
    const float* wq    = (const float*)d_in[4];
    const float* wk    = (const float*)d_in[5];
    const float* wv    = (const float*)d_in[6];
    const float* wo    = (const float*)d_in[7];
    const float* mnw   = (const float*)d_in[8];
    const float* mq    = (const float*)d_in[9];
    const float* mo    = (const float*)d_in[10];
    const float* fnw   = (const float*)d_in[11];
    const float* w1    = (const float*)d_in[12];
    const float* b1    = (const float*)d_in[13];
    const float* w2    = (const float*)d_in[14];
    const float* b2    = (const float*)d_in[15];
    float* out = (float*)d_out;

    const int QKV_SMEM  = (3*4224 + 64) * 4 + 8*128*8;            // 59,136
    const int ATT_SMEM  = 32768 + 33024 + 4096;                   // 69,888
    const int MEM1_SMEM = 64*72*2;                                // 9,216
    const int MEM2_SMEM = (2112 + 2080 + 64) * 4 + 8*96*8;        // 23,168
    const int FFN1_SMEM = 36864 + 18432 + (256 + 64) * 4;         // 56,576
    const int FFN2_SMEM = 64*264*2 + 64*4;                        // 34,048

    cudaFuncSetAttribute(qkv_kernel, cudaFuncAttributeMaxDynamicSharedMemorySize, QKV_SMEM);
    cudaFuncSetAttribute(attn_kernel, cudaFuncAttributeMaxDynamicSharedMemorySize, ATT_SMEM);
    cudaFuncSetAttribute(mem1_kernel, cudaFuncAttributeMaxDynamicSharedMemorySize, MEM1_SMEM);
    cudaFuncSetAttribute(mem2_kernel, cudaFuncAttributeMaxDynamicSharedMemorySize, MEM2_SMEM);
    cudaFuncSetAttribute(mem3_kernel, cudaFuncAttributeMaxDynamicSharedMemorySize, MEM1_SMEM);
    cudaFuncSetAttribute(ffn1_kernel, cudaFuncAttributeMaxDynamicSharedMemorySize, FFN1_SMEM);
    cudaFuncSetAttribute(ffn2_kernel, cudaFuncAttributeMaxDynamicSharedMemorySize, FFN2_SMEM);

    cvt_kernel<<<64, 256>>>(w1, w2, wo, mo);
    qkv_kernel<<<296, 256, QKV_SMEM>>>(x, anw, wq, wk, wv);
    attn_kernel<<<1024, 128, ATT_SMEM>>>();
    mem1_kernel<<<256, 256, MEM1_SMEM>>>(x, out);
    mem2_kernel<<<592, 256, MEM2_SMEM>>>(mvals, maddr, mnw, mq, out);
    mem3_kernel<<<256, 128, MEM1_SMEM>>>(out);
    ffn1_kernel<<<256, 256, FFN1_SMEM>>>(fnw, b1, out);
    ffn2_kernel<<<256, 128, FFN2_SMEM>>>(b2, out);
}

// round 16
// speedup vs baseline: 1.1526x; 1.0949x over previous
#include <cuda_runtime.h>
#include <cuda_bf16.h>
#include <math.h>

#define B_  32
#define S_  1024
#define E_  64
#define H_  4
#define HD_ 16
#define HID_ 256
#define AD_ 32
#define NS_ 64
#define NT_ (B_*S_)
#define QSCALE (0.25f * 1.4426950408889634f)

__device__ __align__(16) __nv_bfloat16 g_qh[B_*H_*S_*HD_];
__device__ __align__(16) __nv_bfloat16 g_kh[B_*H_*S_*HD_];
__device__ __align__(16) __nv_bfloat16 g_vt[B_*H_*HD_*S_];
__device__ __align__(16) __nv_bfloat16 g_ob[(size_t)NT_*E_];      // attn out, bf16
__device__ __align__(16) __nv_bfloat16 g_rv[(size_t)NT_*E_];      // read_vals bf16
__device__ __align__(16) __nv_bfloat16 g_hidb[(size_t)NT_*HID_];
__device__ __align__(16) __nv_bfloat16 g_w1b[HID_*E_];
__device__ __align__(16) __nv_bfloat16 g_w2b[E_*HID_];
__device__ __align__(16) __nv_bfloat16 g_wob[E_*E_];
__device__ __align__(16) __nv_bfloat16 g_mob[E_*E_];

__device__ __forceinline__ unsigned long long pk2(float lo, float hi) {
    unsigned long long r; asm("mov.b64 %0,{%1,%2};" : "=l"(r) : "f"(lo), "f"(hi)); return r;
}
__device__ __forceinline__ float2 upk2(unsigned long long v) {
    float2 f; asm("mov.b64 {%0,%1},%2;" : "=f"(f.x), "=f"(f.y) : "l"(v)); return f;
}
__device__ __forceinline__ unsigned long long ffma2_(unsigned long long a,
    unsigned long long b, unsigned long long c) {
    unsigned long long d;
    asm("fma.rn.f32x2 %0,%1,%2,%3;" : "=l"(d) : "l"(a), "l"(b), "l"(c)); return d;
}
__device__ __forceinline__ float ex2_(float x) {
    float y; asm("ex2.approx.f32 %0,%1;" : "=f"(y) : "f"(x)); return y;
}
__device__ __forceinline__ float gelu_(float v) {
    float u = v * (0.7978845608f + 0.0356774081f * v * v);
    float e = ex2_(u * 2.885390082f);
    float r; asm("rcp.approx.f32 %0,%1;" : "=f"(r) : "f"(1.f + e));
    return 0.5f * v * (2.f - 2.f*r);
}
__device__ __forceinline__ unsigned pbf_(float lo, float hi) {
    unsigned r; asm("cvt.rn.bf16x2.f32 %0,%1,%2;" : "=r"(r) : "f"(hi), "f"(lo)); return r;
}
__device__ __forceinline__ void mma16816(float& c0, float& c1, float& c2, float& c3,
    unsigned a0, unsigned a1, unsigned a2, unsigned a3, unsigned b0, unsigned b1) {
    asm volatile("mma.sync.aligned.m16n8k16.row.col.f32.bf16.bf16.f32 "
        "{%0,%1,%2,%3},{%4,%5,%6,%7},{%8,%9},{%0,%1,%2,%3};"
        : "+f"(c0), "+f"(c1), "+f"(c2), "+f"(c3)
        : "r"(a0), "r"(a1), "r"(a2), "r"(a3), "r"(b0), "r"(b1));
}

// ============ kernel 0: pre-convert weights to bf16 ============
__global__ void __launch_bounds__(256) cvt_kernel(
    const float* __restrict__ w1, const float* __restrict__ w2,
    const float* __restrict__ wo, const float* __restrict__ mo)
{
    int i = blockIdx.x*256 + threadIdx.x;
    if (i < HID_*E_) {
        g_w1b[i] = __float2bfloat16(w1[i]);
        g_w2b[i] = __float2bfloat16(w2[i]);
    }
    if (i < E_*E_) {
        g_wob[i] = __float2bfloat16(wo[i]);
        g_mob[i] = __float2bfloat16(mo[i]);
    }
}

// ============ kernel 1: rmsnorm + QKV via HMMA ============
// block = 128 tokens, 256 threads. B = [wq;wk;wv] stacked [192][72].
// 8 warps = 4 token-quarters x 2 n-halves (96 outputs each, 2 chunks of 48).
__global__ void __launch_bounds__(256, 2) qkv_kernel(
    const float* __restrict__ x, const float* __restrict__ nw,
    const float* __restrict__ wq, const float* __restrict__ wk,
    const float* __restrict__ wv)
{
    extern __shared__ char smc[];
    __nv_bfloat16* Bs = (__nv_bfloat16*)smc;             // [192][72] 27648
    __nv_bfloat16* As = (__nv_bfloat16*)(smc + 27648);   // [128][72] 18432
    float* nws = (float*)(smc + 27648 + 18432);          // 64

    const int tid = threadIdx.x, lane = tid & 31, w = tid >> 5;
    const int g = lane >> 2, tg = lane & 3;
    const int wm = w & 3, nh = w >> 2;
    const int tok0 = blockIdx.x * 128;

    for (int i = tid; i < 4096; i += 256) {
        int o = i >> 6, j = i & 63;
        Bs[o*72 + j]         = __float2bfloat16(wq[i]);
        Bs[(o + 64)*72 + j]  = __float2bfloat16(wk[i]);
        Bs[(o + 128)*72 + j] = __float2bfloat16(wv[i]);
    }
    if (tid < 64) nws[tid] = nw[tid];
    __syncthreads();

    // rmsnorm: one token per thread -> bf16 A tile
    if (tid < 128) {
        const float4* xr = (const float4*)(x + (size_t)(tok0 + tid)*64);
        float4 v[16];
        float ss = 0.f;
        #pragma unroll
        for (int i = 0; i < 16; i++) {
            v[i] = xr[i];
            ss += v[i].x*v[i].x + v[i].y*v[i].y + v[i].z*v[i].z + v[i].w*v[i].w;
        }
        float rinv = rsqrtf(ss * (1.f/64.f) + 1e-5f);
        #pragma unroll
        for (int i = 0; i < 16; i++) {
            *(unsigned*)&As[tid*72 + 4*i]     = pbf_(v[i].x*rinv*nws[4*i],   v[i].y*rinv*nws[4*i+1]);
            *(unsigned*)&As[tid*72 + 4*i + 2] = pbf_(v[i].z*rinv*nws[4*i+2], v[i].w*rinv*nws[4*i+3]);
        }
    }
    __syncthreads();

    unsigned a[4][2][4];
    #pragma unroll
    for (int ks = 0; ks < 4; ks++)
        #pragma unroll
        for (int mf = 0; mf < 2; mf++) {
            int r = wm*32 + mf*16 + g;
            int k = ks*16 + 2*tg;
            a[ks][mf][0] = *(const unsigned*)&As[ r      *72 + k];
            a[ks][mf][1] = *(const unsigned*)&As[(r + 8) *72 + k];
            a[ks][mf][2] = *(const unsigned*)&As[ r      *72 + k + 8];
            a[ks][mf][3] = *(const unsigned*)&As[(r + 8) *72 + k + 8];
        }

    #pragma unroll
    for (int ch = 0; ch < 2; ch++) {
        const int n0 = nh*96 + ch*48;
        float c[2][6][4];
        #pragma unroll
        for (int mf = 0; mf < 2; mf++)
            #pragma unroll
            for (int nf = 0; nf < 6; nf++)
                c[mf][nf][0] = c[mf][nf][1] = c[mf][nf][2] = c[mf][nf][3] = 0.f;

        #pragma unroll
        for (int ks = 0; ks < 4; ks++) {
            #pragma unroll
            for (int nf = 0; nf < 6; nf++) {
                const __nv_bfloat16* br = Bs + (n0 + nf*8 + g)*72 + ks*16 + 2*tg;
                unsigned b0 = *(const unsigned*)br;
                unsigned bq = *(const unsigned*)(br + 8);
                #pragma unroll
                for (int mf = 0; mf < 2; mf++)
                    mma16816(c[mf][nf][0], c[mf][nf][1], c[mf][nf][2], c[mf][nf][3],
                             a[ks][mf][0], a[ks][mf][1], a[ks][mf][2], a[ks][mf][3],
                             b0, bq);
            }
        }

        #pragma unroll
        for (int nf = 0; nf < 6; nf++) {
            const int ebase = n0 + nf*8;       // warp-uniform
            const int p = ebase >> 6;          // 0=q 1=k 2=v, warp-uniform
            const int eb = ebase & 63;
            #pragma unroll
            for (int mf = 0; mf < 2; mf++) {
                int r = tok0 + wm*32 + mf*16 + g;
                int s = r & 1023, bb = r >> 10;
                int e = eb + 2*tg;
                int hh = e >> 4, d = e & 15;
                size_t bhi = (size_t)(bb*H_ + hh);
                float c0 = c[mf][nf][0], c1 = c[mf][nf][1];
                float c2 = c[mf][nf][2], c3 = c[mf][nf][3];
                if (p == 0) {
                    *(unsigned*)&g_qh[(bhi*S_ + s  )*16 + d] = pbf_(c0*QSCALE, c1*QSCALE);
                    *(unsigned*)&g_qh[(bhi*S_ + s+8)*16 + d] = pbf_(c2*QSCALE, c3*QSCALE);
                } else if (p == 1) {
                    *(unsigned*)&g_kh[(bhi*S_ + s  )*16 + d] = pbf_(c0, c1);
                    *(unsigned*)&g_kh[(bhi*S_ + s+8)*16 + d] = pbf_(c2, c3);
                } else {
                    g_vt[(bhi*16 + d  )*S_ + s  ] = __float2bfloat16(c0);
                    g_vt[(bhi*16 + d+1)*S_ + s  ] = __float2bfloat16(c1);
                    g_vt[(bhi*16 + d  )*S_ + s+8] = __float2bfloat16(c2);
                    g_vt[(bhi*16 + d+1)*S_ + s+8] = __float2bfloat16(c3);
                }
            }
        }
    }
}

// ============ kernel 2: causal attention via bf16 HMMA (bf16 output) ============
__global__ void __launch_bounds__(128, 3) attn_kernel()
{
    const int bidx = blockIdx.x;
    const int qt = 7 - (bidx >> 7);          // heavy tiles first
    const int bh = bidx & 127;
    const int nk = (qt + 1) * 128;
    const int qbase = qt * 128;

    extern __shared__ char smc[];
    __nv_bfloat16* Ks = (__nv_bfloat16*)smc;                    // [nk][16]
    __nv_bfloat16* Vt = (__nv_bfloat16*)(smc + 32768);          // [16][1032]
    __nv_bfloat16* Qs = (__nv_bfloat16*)(smc + 32768 + 33024);  // [128][16]

    const int tid = threadIdx.x, lane = tid & 31, w = tid >> 5;

    {
        const uint4* src = (const uint4*)(g_kh + (size_t)bh * S_ * 16);
        uint4* dst = (uint4*)Ks;
        for (int i = tid; i < nk*2; i += 128) dst[i] = src[i];
    }
    {
        const uint4* src = (const uint4*)(g_qh + ((size_t)bh * S_ + qbase) * 16);
        uint4* dst = (uint4*)Qs;
        dst[tid] = src[tid];
        dst[tid + 128] = src[tid + 128];
    }
    for (int d = w; d < 16; d += 4) {
        const uint4* src = (const uint4*)(g_vt + ((size_t)bh*16 + d) * S_);
        uint4* dst = (uint4*)(Vt + d * 1032);
        for (int i = lane; i < nk/8; i += 32) dst[i] = src[i];
    }
    __syncthreads();

    const int g = lane >> 2, tg = lane & 3;

    unsigned qa[2][4];
    #pragma unroll
    for (int mf = 0; mf < 2; mf++) {
        int rr = w*32 + mf*16 + g;
        qa[mf][0] = *(const unsigned*)&Qs[ rr     *16 + 2*tg    ];
        qa[mf][1] = *(const unsigned*)&Qs[(rr + 8)*16 + 2*tg    ];
        qa[mf][2] = *(const unsigned*)&Qs[ rr     *16 + 2*tg + 8];
        qa[mf][3] = *(const unsigned*)&Qs[(rr + 8)*16 + 2*tg + 8];
    }

    float o[2][2][4];
    #pragma unroll
    for (int mf = 0; mf < 2; mf++)
        #pragma unroll
        for (int dh = 0; dh < 2; dh++)
            o[mf][dh][0] = o[mf][dh][1] = o[mf][dh][2] = o[mf][dh][3] = 0.f;
    float lsum[2][2] = {{0.f,0.f},{0.f,0.f}};

    auto step = [&](int j0, bool MASK) {
        unsigned kb[2][2], vb[2][2];
        #pragma unroll
        for (int kh = 0; kh < 2; kh++) {
            const __nv_bfloat16* kr = Ks + (j0 + kh*8 + g)*16 + 2*tg;
            kb[kh][0] = *(const unsigned*)kr;
            kb[kh][1] = *(const unsigned*)(kr + 8);
        }
        #pragma unroll
        for (int dh = 0; dh < 2; dh++) {
            const __nv_bfloat16* vr = Vt + (dh*8 + g)*1032 + j0 + 2*tg;
            vb[dh][0] = *(const unsigned*)vr;
            vb[dh][1] = *(const unsigned*)(vr + 8);
        }
        #pragma unroll
        for (int mf = 0; mf < 2; mf++) {
            float c[2][4];
            #pragma unroll
            for (int kh = 0; kh < 2; kh++) {
                c[kh][0] = c[kh][1] = c[kh][2] = c[kh][3] = 0.f;
                mma16816(c[kh][0], c[kh][1], c[kh][2], c[kh][3],
                         qa[mf][0], qa[mf][1], qa[mf][2], qa[mf][3],
                         kb[kh][0], kb[kh][1]);
            }
            const int r0 = qbase + w*32 + mf*16 + g, r1 = r0 + 8;
            float p[2][4];
            #pragma unroll
            for (int kh = 0; kh < 2; kh++) {
                int k0 = j0 + kh*8 + 2*tg;
                p[kh][0] = (!MASK || k0     <= r0) ? ex2_(c[kh][0]) : 0.f;
                p[kh][1] = (!MASK || k0 + 1 <= r0) ? ex2_(c[kh][1]) : 0.f;
                p[kh][2] = (!MASK || k0     <= r1) ? ex2_(c[kh][2]) : 0.f;
                p[kh][3] = (!MASK || k0 + 1 <= r1) ? ex2_(c[kh][3]) : 0.f;
            }
            lsum[mf][0] += (p[0][0] + p[0][1]) + (p[1][0] + p[1][1]);
            lsum[mf][1] += (p[0][2] + p[0][3]) + (p[1][2] + p[1][3]);
            unsigned pa0 = pbf_(p[0][0], p[0][1]);
            unsigned pa1 = pbf_(p[0][2], p[0][3]);
            unsigned pa2 = pbf_(p[1][0], p[1][1]);
            unsigned pa3 = pbf_(p[1][2], p[1][3]);
            #pragma unroll
            for (int dh = 0; dh < 2; dh++)
                mma16816(o[mf][dh][0], o[mf][dh][1], o[mf][dh][2], o[mf][dh][3],
                         pa0, pa1, pa2, pa3, vb[dh][0], vb[dh][1]);
        }
    };

    for (int j0 = 0; j0 < qbase; j0 += 16) step(j0, false);
    const int wlast = qbase + w*32 + 31;
    for (int j0 = qbase; j0 < nk; j0 += 16) {
        if (j0 > wlast) break;
        step(j0, true);
    }

    const int b = bh >> 2, h = bh & 3;
    #pragma unroll
    for (int mf = 0; mf < 2; mf++) {
        float l0 = lsum[mf][0], l1 = lsum[mf][1];
        l0 += __shfl_xor_sync(~0u, l0, 1); l0 += __shfl_xor_sync(~0u, l0, 2);
        l1 += __shfl_xor_sync(~0u, l1, 1); l1 += __shfl_xor_sync(~0u, l1, 2);
        float i0 = 1.f / l0, i1 = 1.f / l1;
        int r0 = qbase + w*32 + mf*16 + g;
        __nv_bfloat16* b0p = g_ob + (size_t)(b*S_ + r0)*64 + h*16;
        __nv_bfloat16* b1p = b0p + 8*64;
        *(unsigned*)(b0p + 2*tg)     = pbf_(o[mf][0][0]*i0, o[mf][0][1]*i0);
        *(unsigned*)(b0p + 8 + 2*tg) = pbf_(o[mf][1][0]*i0, o[mf][1][1]*i0);
        *(unsigned*)(b1p + 2*tg)     = pbf_(o[mf][0][2]*i1, o[mf][0][3]*i1);
        *(unsigned*)(b1p + 8 + 2*tg) = pbf_(o[mf][1][2]*i1, o[mf][1][3]*i1);
    }
}

// ============ kernel 3a: x1 = x + av@wo^T  (HMMA, 16 tok/warp) ============
__global__ void __launch_bounds__(256) mem1_kernel(
    const float* __restrict__ x, float* __restrict__ out)
{
    extern __shared__ char smc[];
    __nv_bfloat16* woB = (__nv_bfloat16*)smc;   // [64][72]

    const int tid = threadIdx.x, lane = tid & 31, w = tid >> 5;
    const int g = lane >> 2, tg = lane & 3;
    const int m0 = blockIdx.x*128 + w*16;

    for (int i = tid; i < 2048; i += 256) {
        int o = i >> 5, j = (i & 31)*2;
        *(unsigned*)&woB[o*72 + j] = ((const unsigned*)g_wob)[i];
    }
    __syncthreads();

    float c[8][4];
    #pragma unroll
    for (int nf = 0; nf < 8; nf++)
        c[nf][0] = c[nf][1] = c[nf][2] = c[nf][3] = 0.f;

    #pragma unroll
    for (int ks = 0; ks < 4; ks++) {
        const int k = ks*16 + 2*tg;
        const __nv_bfloat16* ar = g_ob + (size_t)(m0 + g)*64 + k;
        unsigned a0 = *(const unsigned*)ar;
        unsigned a1 = *(const unsigned*)(ar + 8*64);
        unsigned a2 = *(const unsigned*)(ar + 8);
        unsigned a3 = *(const unsigned*)(ar + 8*64 + 8);
        #pragma unroll
        for (int nf = 0; nf < 8; nf++) {
            const __nv_bfloat16* br = woB + (nf*8 + g)*72 + k;
            mma16816(c[nf][0], c[nf][1], c[nf][2], c[nf][3],
                     a0, a1, a2, a3,
                     *(const unsigned*)br, *(const unsigned*)(br + 8));
        }
    }

    const int r = m0 + g;
    #pragma unroll
    for (int nf = 0; nf < 8; nf++) {
        int e = nf*8 + 2*tg;
        float2 x0 = *(const float2*)&x[(size_t)r*64 + e];
        float2 x1 = *(const float2*)&x[(size_t)(r+8)*64 + e];
        *(float2*)&out[(size_t)r*64 + e] =
            make_float2(x0.x + c[nf][0], x0.y + c[nf][1]);
        *(float2*)&out[(size_t)(r+8)*64 + e] =
            make_float2(x1.x + c[nf][2], x1.y + c[nf][3]);
    }
}

// ============ kernel 3b: fp32 middle, token-pair f32x2 packed ============
__global__ void __launch_bounds__(256) mem2_kernel(
    const float* __restrict__ mvals, const float* __restrict__ maddr,
    const float* __restrict__ mnw,   const float* __restrict__ mq,
    const float* __restrict__ out)
{
    extern __shared__ float sm[];
    float* mqT  = sm;              // [64][33]
    float* aT   = mqT + 2112;      // [32][65]
    float* mnws = aT + 2080;       // 64
    unsigned long long* u64base = (unsigned long long*)(mnws + 64);  // 8w * 96

    const int tid = threadIdx.x, lane = tid & 31, w = tid >> 5;

    for (int i = tid; i < AD_*E_; i += blockDim.x) {
        int a = i >> 6, e = i & 63;
        mqT[e*33 + a] = mq[i];
    }
    if (tid < 64) mnws[tid] = mnw[tid];
    if (tid < 64) {
        float ssum = 0.f, v[32];
        #pragma unroll
        for (int a = 0; a < 32; a++) { v[a] = maddr[tid*32 + a]; ssum += v[a]*v[a]; }
        float rn = 1.f / fmaxf(sqrtf(ssum), 1e-12f);
        #pragma unroll
        for (int a = 0; a < 32; a++) aT[a*65 + tid] = v[a] * rn;
    }
    __syncthreads();

    unsigned long long* hp = u64base + w*96;   // 64 u64
    unsigned long long* qp = hp + 64;          // 32 u64

    for (int pr = blockIdx.x*8 + w; pr < NT_/2; pr += gridDim.x*8) {
        const int tok0 = pr*2, tok1 = tok0 + 1;
        float a0 = out[(size_t)tok0*64 + lane];
        float b0 = out[(size_t)tok0*64 + lane + 32];
        float a1 = out[(size_t)tok1*64 + lane];
        float b1 = out[(size_t)tok1*64 + lane + 32];
        float ss0 = a0*a0 + b0*b0, ss1 = a1*a1 + b1*b1;
        #pragma unroll
        for (int o = 16; o; o >>= 1) {
            ss0 += __shfl_xor_sync(~0u, ss0, o);
            ss1 += __shfl_xor_sync(~0u, ss1, o);
        }
        float ri0 = rsqrtf(ss0 * (1.f/64.f) + 1e-5f);
        float ri1 = rsqrtf(ss1 * (1.f/64.f) + 1e-5f);
        float w0 = mnws[lane], w1 = mnws[lane + 32];
        hp[lane]      = pk2(a0*ri0*w0, a1*ri1*w0);
        hp[lane + 32] = pk2(b0*ri0*w1, b1*ri1*w1);
        __syncwarp();

        unsigned long long qacc = 0ull;
        #pragma unroll 8
        for (int e = 0; e < 64; e++) {
            float mw = mqT[e*33 + lane];
            qacc = ffma2_(pk2(mw, mw), hp[e], qacc);
        }
        float2 qf = upk2(qacc);
        float qs0 = qf.x*qf.x, qs1 = qf.y*qf.y;
        #pragma unroll
        for (int o = 16; o; o >>= 1) {
            qs0 += __shfl_xor_sync(~0u, qs0, o);
            qs1 += __shfl_xor_sync(~0u, qs1, o);
        }
        float rq0 = 1.f / fmaxf(sqrtf(qs0), 1e-12f);
        float rq1 = 1.f / fmaxf(sqrtf(qs1), 1e-12f);
        qp[lane] = pk2(qf.x*rq0, qf.y*rq1);
        __syncwarp();

        unsigned long long s0acc = 0ull, s1acc = 0ull;
        #pragma unroll 8
        for (int a = 0; a < 32; a++) {
            unsigned long long qv = qp[a];
            float wa = aT[a*65 + lane], wb = aT[a*65 + lane + 32];
            s0acc = ffma2_(pk2(wa, wa), qv, s0acc);
            s1acc = ffma2_(pk2(wb, wb), qv, s1acc);
        }
        float2 s0f = upk2(s0acc), s1f = upk2(s1acc);

        #pragma unroll
        for (int t = 0; t < 2; t++) {
            const int tok = tok0 + t;
            const int b = tok >> 10;
            float sc0 = (t == 0 ? s0f.x : s0f.y) * 4.f;
            float sc1 = (t == 0 ? s1f.x : s1f.y) * 4.f;
            unsigned f0 = __float_as_uint(sc0);
            unsigned m0 = (f0 & 0x80000000u) ? ~f0 : (f0 | 0x80000000u);
            unsigned key0 = (m0 & 0xFFFFFFC0u) | (unsigned)(63 - lane);
            unsigned f1 = __float_as_uint(sc1);
            unsigned m1 = (f1 & 0x80000000u) ? ~f1 : (f1 | 0x80000000u);
            unsigned key1 = (m1 & 0xFFFFFFC0u) | (unsigned)(31 - lane);
            float tv[8]; int ti[8];
            #pragma unroll
            for (int k = 0; k < 8; k++) {
                unsigned loc = key0 > key1 ? key0 : key1;
                unsigned r = __reduce_max_sync(0xffffffffu, loc);
                int idx = 63 - (int)(r & 63u);
                float vsel = __shfl_sync(0xffffffffu, (idx >= 32) ? sc1 : sc0, idx & 31);
                tv[k] = vsel; ti[k] = idx;
                if (idx == lane)      key0 = 0u;
                if (idx == lane + 32) key1 = 0u;
            }
            float wsum = 0.f, wk8[8];
            #pragma unroll
            for (int k = 0; k < 8; k++) { wk8[k] = __expf(tv[k] - tv[0]); wsum += wk8[k]; }
            float winv = 1.f / wsum;
            const float* mb = mvals + b * NS_ * E_;
            float r0 = 0.f, r1 = 0.f;
            #pragma unroll
            for (int k = 0; k < 8; k++) {
                float wv = wk8[k] * winv;
                const float* mrow = mb + ti[k]*64;
                r0 += wv * mrow[lane];
                r1 += wv * mrow[lane + 32];
            }
            g_rv[(size_t)tok*64 + lane]      = __float2bfloat16(r0);
            g_rv[(size_t)tok*64 + lane + 32] = __float2bfloat16(r1);
        }
    }
}

// ============ kernel 3c: out += rv@mo^T  (HMMA) ============
__global__ void __launch_bounds__(128, 4) mem3_kernel(float* __restrict__ out)
{
    extern __shared__ char smc[];
    __nv_bfloat16* moB = (__nv_bfloat16*)smc;   // [64][72]

    const int tid = threadIdx.x, lane = tid & 31, w = tid >> 5;
    const int g = lane >> 2, tg = lane & 3;
    const int m0 = blockIdx.x*128 + w*32;

    for (int i = tid; i < 2048; i += 128) {
        int o = i >> 5, j = (i & 31)*2;
        *(unsigned*)&moB[o*72 + j] = ((const unsigned*)g_mob)[i];
    }
    __syncthreads();

    float c[2][8][4];
    #pragma unroll
    for (int mf = 0; mf < 2; mf++)
        #pragma unroll
        for (int nf = 0; nf < 8; nf++)
            c[mf][nf][0] = c[mf][nf][1] = c[mf][nf][2] = c[mf][nf][3] = 0.f;

    #pragma unroll
    for (int ks = 0; ks < 4; ks++) {
        const int k = ks*16 + 2*tg;
        unsigned a[2][4];
        #pragma unroll
        for (int mf = 0; mf < 2; mf++) {
            const __nv_bfloat16* ar = g_rv + (size_t)(m0 + mf*16 + g)*64 + k;
            a[mf][0] = *(const unsigned*)ar;
            a[mf][1] = *(const unsigned*)(ar + 8*64);
            a[mf][2] = *(const unsigned*)(ar + 8);
            a[mf][3] = *(const unsigned*)(ar + 8*64 + 8);
        }
        #pragma unroll
        for (int nf = 0; nf < 8; nf++) {
            const __nv_bfloat16* br = moB + (nf*8 + g)*72 + k;
            unsigned b0 = *(const unsigned*)br;
            unsigned bq = *(const unsigned*)(br + 8);
            #pragma unroll
            for (int mf = 0; mf < 2; mf++)
                mma16816(c[mf][nf][0], c[mf][nf][1], c[mf][nf][2], c[mf][nf][3],
                         a[mf][0], a[mf][1], a[mf][2], a[mf][3], b0, bq);
        }
    }

    #pragma unroll
    for (int mf = 0; mf < 2; mf++) {
        const int r = m0 + mf*16 + g;
        #pragma unroll
        for (int nf = 0; nf < 8; nf++) {
            int e = nf*8 + 2*tg;
            float2 o0 = *(float2*)&out[(size_t)r*64 + e];
            float2 o1 = *(float2*)&out[(size_t)(r+8)*64 + e];
            o0.x += c[mf][nf][0]; o0.y += c[mf][nf][1];
            o1.x += c[mf][nf][2]; o1.y += c[mf][nf][3];
            *(float2*)&out[(size_t)r*64 + e]     = o0;
            *(float2*)&out[(size_t)(r+8)*64 + e] = o1;
        }
    }
}

// ============ kernel 4a: FFN GEMM1 via HMMA + fast GELU -> g_hidb ============
__global__ void __launch_bounds__(256, 2) ffn1_kernel(
    const float* __restrict__ fnw, const float* __restrict__ b1,
    const float* __restrict__ out)
{
    extern __shared__ char smc[];
    __nv_bfloat16* w1s = (__nv_bfloat16*)smc;            // [256][72]
    __nv_bfloat16* As  = (__nv_bfloat16*)(smc + 36864);  // [128][72]
    float* b1s = (float*)(smc + 36864 + 18432);          // 256
    float* fns = b1s + 256;                              // 64

    const int tid = threadIdx.x, lane = tid & 31, w = tid >> 5;
    const int g = lane >> 2, tg = lane & 3;
    const int wm = w & 3, nh = w >> 2;
    const int tok0 = blockIdx.x * 128;

    for (int i = tid; i < 256*32; i += 256) {
        int j2 = i*2;
        int o = j2 >> 6, j = j2 & 63;
        *(unsigned*)&w1s[o*72 + j] = ((const unsigned*)g_w1b)[i];
    }
    b1s[tid] = b1[tid];
    if (tid < 64) fns[tid] = fnw[tid];
    __syncthreads();

    if (tid < 128) {
        const float4* xr = (const float4*)(out + (size_t)(tok0 + tid)*64);
        float4 v[16];
        float ss = 0.f;
        #pragma unroll
        for (int i = 0; i < 16; i++) {
            v[i] = xr[i];
            ss += v[i].x*v[i].x + v[i].y*v[i].y + v[i].z*v[i].z + v[i].w*v[i].w;
        }
        float rinv = rsqrtf(ss * (1.f/64.f) + 1e-5f);
        #pragma unroll
        for (int i = 0; i < 16; i++) {
            *(unsigned*)&As[tid*72 + 4*i]     = pbf_(v[i].x*rinv*fns[4*i],   v[i].y*rinv*fns[4*i+1]);
            *(unsigned*)&As[tid*72 + 4*i + 2] = pbf_(v[i].z*rinv*fns[4*i+2], v[i].w*rinv*fns[4*i+3]);
        }
    }
    __syncthreads();

    unsigned a[4][2][4];
    #pragma unroll
    for (int ks = 0; ks < 4; ks++)
        #pragma unroll
        for (int mf = 0; mf < 2; mf++) {
            int r = wm*32 + mf*16 + g;
            int k = ks*16 + 2*tg;
            a[ks][mf][0] = *(const unsigned*)&As[ r      *72 + k];
            a[ks][mf][1] = *(const unsigned*)&As[(r + 8) *72 + k];
            a[ks][mf][2] = *(const unsigned*)&As[ r      *72 + k + 8];
            a[ks][mf][3] = *(const unsigned*)&As[(r + 8) *72 + k + 8];
        }

    #pragma unroll
    for (int ch = 0; ch < 2; ch++) {
        const int n0 = nh*128 + ch*64;
        float c[2][8][4];
        #pragma unroll
        for (int mf = 0; mf < 2; mf++)
            #pragma unroll
            for (int nf = 0; nf < 8; nf++)
                c[mf][nf][0] = c[mf][nf][1] = c[mf][nf][2] = c[mf][nf][3] = 0.f;

        #pragma unroll
        for (int ks = 0; ks < 4; ks++) {
            #pragma unroll
            for (int nf = 0; nf < 8; nf++) {
                const __nv_bfloat16* br = w1s + (n0 + nf*8 + g)*72 + ks*16 + 2*tg;
                unsigned b0 = *(const unsigned*)br;
                unsigned bq = *(const unsigned*)(br + 8);
                #pragma unroll
                for (int mf = 0; mf < 2; mf++)
                    mma16816(c[mf][nf][0], c[mf][nf][1], c[mf][nf][2], c[mf][nf][3],
                             a[ks][mf][0], a[ks][mf][1], a[ks][mf][2], a[ks][mf][3],
                             b0, bq);
            }
        }

        #pragma unroll
        for (int mf = 0; mf < 2; mf++) {
            const int r = tok0 + wm*32 + mf*16 + g;
            #pragma unroll
            for (int nf = 0; nf < 8; nf++) {
                int e = n0 + nf*8 + 2*tg;
                float be0 = b1s[e], be1 = b1s[e+1];
                *(unsigned*)&g_hidb[(size_t)r*256 + e] =
                    pbf_(gelu_(c[mf][nf][0] + be0), gelu_(c[mf][nf][1] + be1));
                *(unsigned*)&g_hidb[(size_t)(r+8)*256 + e] =
                    pbf_(gelu_(c[mf][nf][2] + be0), gelu_(c[mf][nf][3] + be1));
            }
        }
    }
}

// ============ kernel 4b: FFN GEMM2 via HMMA + residual ============
__global__ void __launch_bounds__(128, 4) ffn2_kernel(
    const float* __restrict__ b2, float* __restrict__ out)
{
    extern __shared__ char smc[];
    __nv_bfloat16* w2s = (__nv_bfloat16*)smc;   // [64][264]
    float* b2s = (float*)(smc + 64*264*2);

    const int tid = threadIdx.x, lane = tid & 31, w = tid >> 5;
    const int g = lane >> 2, tg = lane & 3;
    const int tok0 = blockIdx.x * 128;

    for (int i = tid; i < 64*128; i += 128) {
        int j2 = i*2;
        int e = j2 >> 8, o = j2 & 255;
        *(unsigned*)&w2s[e*264 + o] = ((const unsigned*)g_w2b)[i];
    }
    if (tid < 64) b2s[tid] = b2[tid];
    __syncthreads();

    float c[2][8][4];
    #pragma unroll
    for (int mf = 0; mf < 2; mf++)
        #pragma unroll
        for (int nf = 0; nf < 8; nf++)
            c[mf][nf][0] = c[mf][nf][1] = c[mf][nf][2] = c[mf][nf][3] = 0.f;

    const int m0 = tok0 + w*32;
    #pragma unroll 4
    for (int ks = 0; ks < 16; ks++) {
        const int k = ks*16 + 2*tg;
        unsigned a[2][4];
        #pragma unroll
        for (int mf = 0; mf < 2; mf++) {
            const __nv_bfloat16* ar = g_hidb + (size_t)(m0 + mf*16 + g)*256 + k;
            a[mf][0] = *(const unsigned*)ar;
            a[mf][1] = *(const unsigned*)(ar + 8*256);
            a[mf][2] = *(const unsigned*)(ar + 8);
            a[mf][3] = *(const unsigned*)(ar + 8*256 + 8);
        }
        #pragma unroll
        for (int nf = 0; nf < 8; nf++) {
            const __nv_bfloat16* br = w2s + (nf*8 + g)*264 + k;
            unsigned b0 = *(const unsigned*)br;
            unsigned bq = *(const unsigned*)(br + 8);
            #pragma unroll
            for (int mf = 0; mf < 2; mf++)
                mma16816(c[mf][nf][0], c[mf][nf][1], c[mf][nf][2], c[mf][nf][3],
                         a[mf][0], a[mf][1], a[mf][2], a[mf][3], b0, bq);
        }
    }

    #pragma unroll
    for (int mf = 0; mf < 2; mf++) {
        const int r = m0 + mf*16 + g;
        #pragma unroll
        for (int nf = 0; nf < 8; nf++) {
            int e = nf*8 + 2*tg;
            float2 o0 = *(float2*)&out[(size_t)r*64 + e];
            float2 o1 = *(float2*)&out[(size_t)(r+8)*64 + e];
            o0.x += b2s[e]   + c[mf][nf][0];
            o0.y += b2s[e+1] + c[mf][nf][1];
            o1.x += b2s[e]   + c[mf][nf][2];
            o1.y += b2s[e+1] + c[mf][nf][3];
            *(float2*)&out[(size_t)r*64 + e]     = o0;
            *(float2*)&out[(size_t)(r+8)*64 + e] = o1;
        }
    }
}

// ============ launch ============
extern "C" void kernel_launch(void* const* d_in, const int* in_sizes, int n_in,
                              void* d_out, int out_size)
{
    const float* x     = (const float*)d_in[0];
    const float* maddr = (const float*)d_in[1];
    const float* mvals = (const float*)d_in[2];
    const float* anw   = (const float*)d_in[3];
    const float* wq    = (const float*)d_in[4];
    const float* wk    = (const float*)d_in[5];
    const float* wv    = (const float*)d_in[6];
    const float* wo    = (const float*)d_in[7];
    const float* mnw   = (const float*)d_in[8];
    const float* mq    = (const float*)d_in[9];
    const float* mo    = (const float*)d_in[10];
    const float* fnw   = (const float*)d_in[11];
    const float* w1    = (const float*)d_in[12];
    const float* b1    = (const float*)d_in[13];
    const float* w2    = (const float*)d_in[14];
    const float* b2    = (const float*)d_in[15];
    float* out = (float*)d_out;

    const int QKV_SMEM  = 27648 + 18432 + 256;                    // 46,336
    const int ATT_SMEM  = 32768 + 33024 + 4096;                   // 69,888
    const int MEM1_SMEM = 64*72*2;                                // 9,216
    const int MEM2_SMEM = (2112 + 2080 + 64) * 4 + 8*96*8;        // 23,168
    const int FFN1_SMEM = 36864 + 18432 + (256 + 64) * 4;         // 56,576
    const int FFN2_SMEM = 64*264*2 + 64*4;                        // 34,048

    cudaFuncSetAttribute(qkv_kernel, cudaFuncAttributeMaxDynamicSharedMemorySize, QKV_SMEM);
    cudaFuncSetAttribute(attn_kernel, cudaFuncAttributeMaxDynamicSharedMemorySize, ATT_SMEM);
    cudaFuncSetAttribute(mem1_kernel, cudaFuncAttributeMaxDynamicSharedMemorySize, MEM1_SMEM);
    cudaFuncSetAttribute(mem2_kernel, cudaFuncAttributeMaxDynamicSharedMemorySize, MEM2_SMEM);
    cudaFuncSetAttribute(mem3_kernel, cudaFuncAttributeMaxDynamicSharedMemorySize, MEM1_SMEM);
    cudaFuncSetAttribute(ffn1_kernel, cudaFuncAttributeMaxDynamicSharedMemorySize, FFN1_SMEM);
    cudaFuncSetAttribute(ffn2_kernel, cudaFuncAttributeMaxDynamicSharedMemorySize, FFN2_SMEM);

    cvt_kernel<<<64, 256>>>(w1, w2, wo, mo);
    qkv_kernel<<<256, 256, QKV_SMEM>>>(x, anw, wq, wk, wv);
    attn_kernel<<<1024, 128, ATT_SMEM>>>();
    mem1_kernel<<<256, 256, MEM1_SMEM>>>(x, out);
    mem2_kernel<<<592, 256, MEM2_SMEM>>>(mvals, maddr, mnw, mq, out);
    mem3_kernel<<<256, 128, MEM1_SMEM>>>(out);
    ffn1_kernel<<<256, 256, FFN1_SMEM>>>(fnw, b1, out);
    ffn2_kernel<<<256, 128, FFN2_SMEM>>>(b2, out);
}

// round 17
// speedup vs baseline: 1.1955x; 1.0372x over previous
#include <cuda_runtime.h>
#include <cuda_bf16.h>
#include <math.h>

#define B_  32
#define S_  1024
#define E_  64
#define H_  4
#define HD_ 16
#define HID_ 256
#define AD_ 32
#define NS_ 64
#define NT_ (B_*S_)
#define QSCALE (0.25f * 1.4426950408889634f)

__device__ __align__(16) __nv_bfloat16 g_qh[B_*H_*S_*HD_];
__device__ __align__(16) __nv_bfloat16 g_kh[B_*H_*S_*HD_];
__device__ __align__(16) __nv_bfloat16 g_vt[B_*H_*HD_*S_];
__device__ __align__(16) __nv_bfloat16 g_ob[(size_t)NT_*E_];      // attn out, bf16
__device__ __align__(16) __nv_bfloat16 g_rv[(size_t)NT_*E_];      // read_vals bf16
__device__ __align__(16) __nv_bfloat16 g_hidb[(size_t)NT_*HID_];
__device__ __align__(16) __nv_bfloat16 g_w1b[HID_*E_];
__device__ __align__(16) __nv_bfloat16 g_w2b[E_*HID_];
__device__ __align__(16) __nv_bfloat16 g_wob[E_*E_];
__device__ __align__(16) __nv_bfloat16 g_mob[E_*E_];

__device__ __forceinline__ unsigned long long pk2(float lo, float hi) {
    unsigned long long r; asm("mov.b64 %0,{%1,%2};" : "=l"(r) : "f"(lo), "f"(hi)); return r;
}
__device__ __forceinline__ float2 upk2(unsigned long long v) {
    float2 f; asm("mov.b64 {%0,%1},%2;" : "=f"(f.x), "=f"(f.y) : "l"(v)); return f;
}
__device__ __forceinline__ unsigned long long ffma2_(unsigned long long a,
    unsigned long long b, unsigned long long c) {
    unsigned long long d;
    asm("fma.rn.f32x2 %0,%1,%2,%3;" : "=l"(d) : "l"(a), "l"(b), "l"(c)); return d;
}
__device__ __forceinline__ float ex2_(float x) {
    float y; asm("ex2.approx.f32 %0,%1;" : "=f"(y) : "f"(x)); return y;
}
__device__ __forceinline__ float gelu_(float v) {
    float u = v * (0.7978845608f + 0.0356774081f * v * v);
    float e = ex2_(u * 2.885390082f);
    float r; asm("rcp.approx.f32 %0,%1;" : "=f"(r) : "f"(1.f + e));
    return 0.5f * v * (2.f - 2.f*r);
}
__device__ __forceinline__ unsigned pbf_(float lo, float hi) {
    unsigned r; asm("cvt.rn.bf16x2.f32 %0,%1,%2;" : "=r"(r) : "f"(hi), "f"(lo)); return r;
}
__device__ __forceinline__ void mma16816(float& c0, float& c1, float& c2, float& c3,
    unsigned a0, unsigned a1, unsigned a2, unsigned a3, unsigned b0, unsigned b1) {
    asm volatile("mma.sync.aligned.m16n8k16.row.col.f32.bf16.bf16.f32 "
        "{%0,%1,%2,%3},{%4,%5,%6,%7},{%8,%9},{%0,%1,%2,%3};"
        : "+f"(c0), "+f"(c1), "+f"(c2), "+f"(c3)
        : "r"(a0), "r"(a1), "r"(a2), "r"(a3), "r"(b0), "r"(b1));
}

// ============ kernel 0: pre-convert weights to bf16 ============
__global__ void __launch_bounds__(256) cvt_kernel(
    const float* __restrict__ w1, const float* __restrict__ w2,
    const float* __restrict__ wo, const float* __restrict__ mo)
{
    int i = blockIdx.x*256 + threadIdx.x;
    if (i < HID_*E_) {
        g_w1b[i] = __float2bfloat16(w1[i]);
        g_w2b[i] = __float2bfloat16(w2[i]);
    }
    if (i < E_*E_) {
        g_wob[i] = __float2bfloat16(wo[i]);
        g_mob[i] = __float2bfloat16(mo[i]);
    }
}

// ============ kernel 1: rmsnorm + QKV via HMMA ============
__global__ void __launch_bounds__(256, 2) qkv_kernel(
    const float* __restrict__ x, const float* __restrict__ nw,
    const float* __restrict__ wq, const float* __restrict__ wk,
    const float* __restrict__ wv)
{
    extern __shared__ char smc[];
    __nv_bfloat16* Bs = (__nv_bfloat16*)smc;             // [192][72] 27648
    __nv_bfloat16* As = (__nv_bfloat16*)(smc + 27648);   // [128][72] 18432
    float* nws = (float*)(smc + 27648 + 18432);          // 64

    const int tid = threadIdx.x, lane = tid & 31, w = tid >> 5;
    const int g = lane >> 2, tg = lane & 3;
    const int wm = w & 3, nh = w >> 2;
    const int tok0 = blockIdx.x * 128;

    for (int i = tid; i < 4096; i += 256) {
        int o = i >> 6, j = i & 63;
        Bs[o*72 + j]         = __float2bfloat16(wq[i]);
        Bs[(o + 64)*72 + j]  = __float2bfloat16(wk[i]);
        Bs[(o + 128)*72 + j] = __float2bfloat16(wv[i]);
    }
    if (tid < 64) nws[tid] = nw[tid];
    __syncthreads();

    if (tid < 128) {
        const float4* xr = (const float4*)(x + (size_t)(tok0 + tid)*64);
        float4 v[16];
        float ss = 0.f;
        #pragma unroll
        for (int i = 0; i < 16; i++) {
            v[i] = xr[i];
            ss += v[i].x*v[i].x + v[i].y*v[i].y + v[i].z*v[i].z + v[i].w*v[i].w;
        }
        float rinv = rsqrtf(ss * (1.f/64.f) + 1e-5f);
        #pragma unroll
        for (int i = 0; i < 16; i++) {
            *(unsigned*)&As[tid*72 + 4*i]     = pbf_(v[i].x*rinv*nws[4*i],   v[i].y*rinv*nws[4*i+1]);
            *(unsigned*)&As[tid*72 + 4*i + 2] = pbf_(v[i].z*rinv*nws[4*i+2], v[i].w*rinv*nws[4*i+3]);
        }
    }
    __syncthreads();

    unsigned a[4][2][4];
    #pragma unroll
    for (int ks = 0; ks < 4; ks++)
        #pragma unroll
        for (int mf = 0; mf < 2; mf++) {
            int r = wm*32 + mf*16 + g;
            int k = ks*16 + 2*tg;
            a[ks][mf][0] = *(const unsigned*)&As[ r      *72 + k];
            a[ks][mf][1] = *(const unsigned*)&As[(r + 8) *72 + k];
            a[ks][mf][2] = *(const unsigned*)&As[ r      *72 + k + 8];
            a[ks][mf][3] = *(const unsigned*)&As[(r + 8) *72 + k + 8];
        }

    #pragma unroll
    for (int ch = 0; ch < 2; ch++) {
        const int n0 = nh*96 + ch*48;
        float c[2][6][4];
        #pragma unroll
        for (int mf = 0; mf < 2; mf++)
            #pragma unroll
            for (int nf = 0; nf < 6; nf++)
                c[mf][nf][0] = c[mf][nf][1] = c[mf][nf][2] = c[mf][nf][3] = 0.f;

        #pragma unroll
        for (int ks = 0; ks < 4; ks++) {
            #pragma unroll
            for (int nf = 0; nf < 6; nf++) {
                const __nv_bfloat16* br = Bs + (n0 + nf*8 + g)*72 + ks*16 + 2*tg;
                unsigned b0 = *(const unsigned*)br;
                unsigned bq = *(const unsigned*)(br + 8);
                #pragma unroll
                for (int mf = 0; mf < 2; mf++)
                    mma16816(c[mf][nf][0], c[mf][nf][1], c[mf][nf][2], c[mf][nf][3],
                             a[ks][mf][0], a[ks][mf][1], a[ks][mf][2], a[ks][mf][3],
                             b0, bq);
            }
        }

        #pragma unroll
        for (int nf = 0; nf < 6; nf++) {
            const int ebase = n0 + nf*8;
            const int p = ebase >> 6;
            const int eb = ebase & 63;
            #pragma unroll
            for (int mf = 0; mf < 2; mf++) {
                int r = tok0 + wm*32 + mf*16 + g;
                int s = r & 1023, bb = r >> 10;
                int e = eb + 2*tg;
                int hh = e >> 4, d = e & 15;
                size_t bhi = (size_t)(bb*H_ + hh);
                float c0 = c[mf][nf][0], c1 = c[mf][nf][1];
                float c2 = c[mf][nf][2], c3 = c[mf][nf][3];
                if (p == 0) {
                    *(unsigned*)&g_qh[(bhi*S_ + s  )*16 + d] = pbf_(c0*QSCALE, c1*QSCALE);
                    *(unsigned*)&g_qh[(bhi*S_ + s+8)*16 + d] = pbf_(c2*QSCALE, c3*QSCALE);
                } else if (p == 1) {
                    *(unsigned*)&g_kh[(bhi*S_ + s  )*16 + d] = pbf_(c0, c1);
                    *(unsigned*)&g_kh[(bhi*S_ + s+8)*16 + d] = pbf_(c2, c3);
                } else {
                    g_vt[(bhi*16 + d  )*S_ + s  ] = __float2bfloat16(c0);
                    g_vt[(bhi*16 + d+1)*S_ + s  ] = __float2bfloat16(c1);
                    g_vt[(bhi*16 + d  )*S_ + s+8] = __float2bfloat16(c2);
                    g_vt[(bhi*16 + d+1)*S_ + s+8] = __float2bfloat16(c3);
                }
            }
        }
    }
}

// ============ kernel 2: causal attention via bf16 HMMA (bf16 output) ============
__global__ void __launch_bounds__(128, 3) attn_kernel()
{
    const int bidx = blockIdx.x;
    const int qt = 7 - (bidx >> 7);          // heavy tiles first
    const int bh = bidx & 127;
    const int nk = (qt + 1) * 128;
    const int qbase = qt * 128;

    extern __shared__ char smc[];
    __nv_bfloat16* Ks = (__nv_bfloat16*)smc;                    // [nk][16]
    __nv_bfloat16* Vt = (__nv_bfloat16*)(smc + 32768);          // [16][1032]
    __nv_bfloat16* Qs = (__nv_bfloat16*)(smc + 32768 + 33024);  // [128][16]

    const int tid = threadIdx.x, lane = tid & 31, w = tid >> 5;

    {
        const uint4* src = (const uint4*)(g_kh + (size_t)bh * S_ * 16);
        uint4* dst = (uint4*)Ks;
        for (int i = tid; i < nk*2; i += 128) dst[i] = src[i];
    }
    {
        const uint4* src = (const uint4*)(g_qh + ((size_t)bh * S_ + qbase) * 16);
        uint4* dst = (uint4*)Qs;
        dst[tid] = src[tid];
        dst[tid + 128] = src[tid + 128];
    }
    for (int d = w; d < 16; d += 4) {
        const uint4* src = (const uint4*)(g_vt + ((size_t)bh*16 + d) * S_);
        uint4* dst = (uint4*)(Vt + d * 1032);
        for (int i = lane; i < nk/8; i += 32) dst[i] = src[i];
    }
    __syncthreads();

    const int g = lane >> 2, tg = lane & 3;

    unsigned qa[2][4];
    #pragma unroll
    for (int mf = 0; mf < 2; mf++) {
        int rr = w*32 + mf*16 + g;
        qa[mf][0] = *(const unsigned*)&Qs[ rr     *16 + 2*tg    ];
        qa[mf][1] = *(const unsigned*)&Qs[(rr + 8)*16 + 2*tg    ];
        qa[mf][2] = *(const unsigned*)&Qs[ rr     *16 + 2*tg + 8];
        qa[mf][3] = *(const unsigned*)&Qs[(rr + 8)*16 + 2*tg + 8];
    }

    float o[2][2][4];
    #pragma unroll
    for (int mf = 0; mf < 2; mf++)
        #pragma unroll
        for (int dh = 0; dh < 2; dh++)
            o[mf][dh][0] = o[mf][dh][1] = o[mf][dh][2] = o[mf][dh][3] = 0.f;
    float lsum[2][2] = {{0.f,0.f},{0.f,0.f}};

    auto step = [&](int j0, bool MASK) {
        unsigned kb[2][2], vb[2][2];
        #pragma unroll
        for (int kh = 0; kh < 2; kh++) {
            const __nv_bfloat16* kr = Ks + (j0 + kh*8 + g)*16 + 2*tg;
            kb[kh][0] = *(const unsigned*)kr;
            kb[kh][1] = *(const unsigned*)(kr + 8);
        }
        #pragma unroll
        for (int dh = 0; dh < 2; dh++) {
            const __nv_bfloat16* vr = Vt + (dh*8 + g)*1032 + j0 + 2*tg;
            vb[dh][0] = *(const unsigned*)vr;
            vb[dh][1] = *(const unsigned*)(vr + 8);
        }
        #pragma unroll
        for (int mf = 0; mf < 2; mf++) {
            float c[2][4];
            #pragma unroll
            for (int kh = 0; kh < 2; kh++) {
                c[kh][0] = c[kh][1] = c[kh][2] = c[kh][3] = 0.f;
                mma16816(c[kh][0], c[kh][1], c[kh][2], c[kh][3],
                         qa[mf][0], qa[mf][1], qa[mf][2], qa[mf][3],
                         kb[kh][0], kb[kh][1]);
            }
            const int r0 = qbase + w*32 + mf*16 + g, r1 = r0 + 8;
            float p[2][4];
            #pragma unroll
            for (int kh = 0; kh < 2; kh++) {
                int k0 = j0 + kh*8 + 2*tg;
                p[kh][0] = (!MASK || k0     <= r0) ? ex2_(c[kh][0]) : 0.f;
                p[kh][1] = (!MASK || k0 + 1 <= r0) ? ex2_(c[kh][1]) : 0.f;
                p[kh][2] = (!MASK || k0     <= r1) ? ex2_(c[kh][2]) : 0.f;
                p[kh][3] = (!MASK || k0 + 1 <= r1) ? ex2_(c[kh][3]) : 0.f;
            }
            lsum[mf][0] += (p[0][0] + p[0][1]) + (p[1][0] + p[1][1]);
            lsum[mf][1] += (p[0][2] + p[0][3]) + (p[1][2] + p[1][3]);
            unsigned pa0 = pbf_(p[0][0], p[0][1]);
            unsigned pa1 = pbf_(p[0][2], p[0][3]);
            unsigned pa2 = pbf_(p[1][0], p[1][1]);
            unsigned pa3 = pbf_(p[1][2], p[1][3]);
            #pragma unroll
            for (int dh = 0; dh < 2; dh++)
                mma16816(o[mf][dh][0], o[mf][dh][1], o[mf][dh][2], o[mf][dh][3],
                         pa0, pa1, pa2, pa3, vb[dh][0], vb[dh][1]);
        }
    };

    for (int j0 = 0; j0 < qbase; j0 += 16) step(j0, false);
    const int wlast = qbase + w*32 + 31;
    for (int j0 = qbase; j0 < nk; j0 += 16) {
        if (j0 > wlast) break;
        step(j0, true);
    }

    const int b = bh >> 2, h = bh & 3;
    #pragma unroll
    for (int mf = 0; mf < 2; mf++) {
        float l0 = lsum[mf][0], l1 = lsum[mf][1];
        l0 += __shfl_xor_sync(~0u, l0, 1); l0 += __shfl_xor_sync(~0u, l0, 2);
        l1 += __shfl_xor_sync(~0u, l1, 1); l1 += __shfl_xor_sync(~0u, l1, 2);
        float i0 = 1.f / l0, i1 = 1.f / l1;
        int r0 = qbase + w*32 + mf*16 + g;
        __nv_bfloat16* b0p = g_ob + (size_t)(b*S_ + r0)*64 + h*16;
        __nv_bfloat16* b1p = b0p + 8*64;
        *(unsigned*)(b0p + 2*tg)     = pbf_(o[mf][0][0]*i0, o[mf][0][1]*i0);
        *(unsigned*)(b0p + 8 + 2*tg) = pbf_(o[mf][1][0]*i0, o[mf][1][1]*i0);
        *(unsigned*)(b1p + 2*tg)     = pbf_(o[mf][0][2]*i1, o[mf][0][3]*i1);
        *(unsigned*)(b1p + 8 + 2*tg) = pbf_(o[mf][1][2]*i1, o[mf][1][3]*i1);
    }
}

// ============ kernel 3a: x1 = x + av@wo^T  (HMMA, all loads prefetched) ============
__global__ void __launch_bounds__(256) mem1_kernel(
    const float* __restrict__ x, float* __restrict__ out)
{
    extern __shared__ char smc[];
    __nv_bfloat16* woB = (__nv_bfloat16*)smc;   // [64][72]

    const int tid = threadIdx.x, lane = tid & 31, w = tid >> 5;
    const int g = lane >> 2, tg = lane & 3;
    const int m0 = blockIdx.x*128 + w*16;
    const int r = m0 + g;

    for (int i = tid; i < 2048; i += 256) {
        int o = i >> 5, j = (i & 31)*2;
        *(unsigned*)&woB[o*72 + j] = ((const unsigned*)g_wob)[i];
    }

    // prefetch ALL global loads before any compute (max MLP)
    unsigned a[4][4];
    #pragma unroll
    for (int ks = 0; ks < 4; ks++) {
        const int k = ks*16 + 2*tg;
        const __nv_bfloat16* ar = g_ob + (size_t)r*64 + k;
        a[ks][0] = *(const unsigned*)ar;
        a[ks][1] = *(const unsigned*)(ar + 8*64);
        a[ks][2] = *(const unsigned*)(ar + 8);
        a[ks][3] = *(const unsigned*)(ar + 8*64 + 8);
    }
    float2 xr0[8], xr1[8];
    #pragma unroll
    for (int nf = 0; nf < 8; nf++) {
        int e = nf*8 + 2*tg;
        xr0[nf] = *(const float2*)&x[(size_t)r*64 + e];
        xr1[nf] = *(const float2*)&x[(size_t)(r+8)*64 + e];
    }
    __syncthreads();

    float c[8][4];
    #pragma unroll
    for (int nf = 0; nf < 8; nf++)
        c[nf][0] = c[nf][1] = c[nf][2] = c[nf][3] = 0.f;

    #pragma unroll
    for (int ks = 0; ks < 4; ks++) {
        const int k = ks*16 + 2*tg;
        #pragma unroll
        for (int nf = 0; nf < 8; nf++) {
            const __nv_bfloat16* br = woB + (nf*8 + g)*72 + k;
            mma16816(c[nf][0], c[nf][1], c[nf][2], c[nf][3],
                     a[ks][0], a[ks][1], a[ks][2], a[ks][3],
                     *(const unsigned*)br, *(const unsigned*)(br + 8));
        }
    }

    #pragma unroll
    for (int nf = 0; nf < 8; nf++) {
        int e = nf*8 + 2*tg;
        *(float2*)&out[(size_t)r*64 + e] =
            make_float2(xr0[nf].x + c[nf][0], xr0[nf].y + c[nf][1]);
        *(float2*)&out[(size_t)(r+8)*64 + e] =
            make_float2(xr1[nf].x + c[nf][2], xr1[nf].y + c[nf][3]);
    }
}

// ============ kernel 3b: fp32 middle, token-pair f32x2 packed ============
__global__ void __launch_bounds__(256) mem2_kernel(
    const float* __restrict__ mvals, const float* __restrict__ maddr,
    const float* __restrict__ mnw,   const float* __restrict__ mq,
    const float* __restrict__ out)
{
    extern __shared__ float sm[];
    float* mqT  = sm;              // [64][33]
    float* aT   = mqT + 2112;      // [32][65]
    float* mnws = aT + 2080;       // 64
    unsigned long long* u64base = (unsigned long long*)(mnws + 64);  // 8w * 96

    const int tid = threadIdx.x, lane = tid & 31, w = tid >> 5;

    for (int i = tid; i < AD_*E_; i += blockDim.x) {
        int a = i >> 6, e = i & 63;
        mqT[e*33 + a] = mq[i];
    }
    if (tid < 64) mnws[tid] = mnw[tid];
    if (tid < 64) {
        float ssum = 0.f, v[32];
        #pragma unroll
        for (int a = 0; a < 32; a++) { v[a] = maddr[tid*32 + a]; ssum += v[a]*v[a]; }
        float rn = 1.f / fmaxf(sqrtf(ssum), 1e-12f);
        #pragma unroll
        for (int a = 0; a < 32; a++) aT[a*65 + tid] = v[a] * rn;
    }
    __syncthreads();

    unsigned long long* hp = u64base + w*96;   // 64 u64
    unsigned long long* qp = hp + 64;          // 32 u64

    for (int pr = blockIdx.x*8 + w; pr < NT_/2; pr += gridDim.x*8) {
        const int tok0 = pr*2, tok1 = tok0 + 1;
        float a0 = out[(size_t)tok0*64 + lane];
        float b0 = out[(size_t)tok0*64 + lane + 32];
        float a1 = out[(size_t)tok1*64 + lane];
        float b1 = out[(size_t)tok1*64 + lane + 32];
        float ss0 = a0*a0 + b0*b0, ss1 = a1*a1 + b1*b1;
        #pragma unroll
        for (int o = 16; o; o >>= 1) {
            ss0 += __shfl_xor_sync(~0u, ss0, o);
            ss1 += __shfl_xor_sync(~0u, ss1, o);
        }
        float ri0 = rsqrtf(ss0 * (1.f/64.f) + 1e-5f);
        float ri1 = rsqrtf(ss1 * (1.f/64.f) + 1e-5f);
        float w0 = mnws[lane], w1 = mnws[lane + 32];
        hp[lane]      = pk2(a0*ri0*w0, a1*ri1*w0);
        hp[lane + 32] = pk2(b0*ri0*w1, b1*ri1*w1);
        __syncwarp();

        unsigned long long qacc = 0ull;
        #pragma unroll 8
        for (int e = 0; e < 64; e++) {
            float mw = mqT[e*33 + lane];
            qacc = ffma2_(pk2(mw, mw), hp[e], qacc);
        }
        float2 qf = upk2(qacc);
        float qs0 = qf.x*qf.x, qs1 = qf.y*qf.y;
        #pragma unroll
        for (int o = 16; o; o >>= 1) {
            qs0 += __shfl_xor_sync(~0u, qs0, o);
            qs1 += __shfl_xor_sync(~0u, qs1, o);
        }
        float rq0 = 1.f / fmaxf(sqrtf(qs0), 1e-12f);
        float rq1 = 1.f / fmaxf(sqrtf(qs1), 1e-12f);
        qp[lane] = pk2(qf.x*rq0, qf.y*rq1);
        __syncwarp();

        unsigned long long s0acc = 0ull, s1acc = 0ull;
        #pragma unroll 8
        for (int a = 0; a < 32; a++) {
            unsigned long long qv = qp[a];
            float wa = aT[a*65 + lane], wb = aT[a*65 + lane + 32];
            s0acc = ffma2_(pk2(wa, wa), qv, s0acc);
            s1acc = ffma2_(pk2(wb, wb), qv, s1acc);
        }
        float2 s0f = upk2(s0acc), s1f = upk2(s1acc);

        #pragma unroll
        for (int t = 0; t < 2; t++) {
            const int tok = tok0 + t;
            const int b = tok >> 10;
            float sc0 = (t == 0 ? s0f.x : s0f.y) * 4.f;
            float sc1 = (t == 0 ? s1f.x : s1f.y) * 4.f;
            unsigned f0 = __float_as_uint(sc0);
            unsigned m0 = (f0 & 0x80000000u) ? ~f0 : (f0 | 0x80000000u);
            unsigned key0 = (m0 & 0xFFFFFFC0u) | (unsigned)(63 - lane);
            unsigned f1 = __float_as_uint(sc1);
            unsigned m1 = (f1 & 0x80000000u) ? ~f1 : (f1 | 0x80000000u);
            unsigned key1 = (m1 & 0xFFFFFFC0u) | (unsigned)(31 - lane);
            float tv[8]; int ti[8];
            #pragma unroll
            for (int k = 0; k < 8; k++) {
                unsigned loc = key0 > key1 ? key0 : key1;
                unsigned r = __reduce_max_sync(0xffffffffu, loc);
                int idx = 63 - (int)(r & 63u);
                float vsel = __shfl_sync(0xffffffffu, (idx >= 32) ? sc1 : sc0, idx & 31);
                tv[k] = vsel; ti[k] = idx;
                if (idx == lane)      key0 = 0u;
                if (idx == lane + 32) key1 = 0u;
            }
            float wsum = 0.f, wk8[8];
            #pragma unroll
            for (int k = 0; k < 8; k++) { wk8[k] = __expf(tv[k] - tv[0]); wsum += wk8[k]; }
            float winv = 1.f / wsum;
            const float* mb = mvals + b * NS_ * E_;
            float r0 = 0.f, r1 = 0.f;
            #pragma unroll
            for (int k = 0; k < 8; k++) {
                float wv = wk8[k] * winv;
                const float* mrow = mb + ti[k]*64;
                r0 += wv * mrow[lane];
                r1 += wv * mrow[lane + 32];
            }
            g_rv[(size_t)tok*64 + lane]      = __float2bfloat16(r0);
            g_rv[(size_t)tok*64 + lane + 32] = __float2bfloat16(r1);
        }
    }
}

// ============ kernel 3c: out += rv@mo^T  (HMMA, all loads prefetched) ============
__global__ void __launch_bounds__(256) mem3_kernel(float* __restrict__ out)
{
    extern __shared__ char smc[];
    __nv_bfloat16* moB = (__nv_bfloat16*)smc;   // [64][72]

    const int tid = threadIdx.x, lane = tid & 31, w = tid >> 5;
    const int g = lane >> 2, tg = lane & 3;
    const int m0 = blockIdx.x*128 + w*16;
    const int r = m0 + g;

    for (int i = tid; i < 2048; i += 256) {
        int o = i >> 5, j = (i & 31)*2;
        *(unsigned*)&moB[o*72 + j] = ((const unsigned*)g_mob)[i];
    }

    unsigned a[4][4];
    #pragma unroll
    for (int ks = 0; ks < 4; ks++) {
        const int k = ks*16 + 2*tg;
        const __nv_bfloat16* ar = g_rv + (size_t)r*64 + k;
        a[ks][0] = *(const unsigned*)ar;
        a[ks][1] = *(const unsigned*)(ar + 8*64);
        a[ks][2] = *(const unsigned*)(ar + 8);
        a[ks][3] = *(const unsigned*)(ar + 8*64 + 8);
    }
    float2 xr0[8], xr1[8];
    #pragma unroll
    for (int nf = 0; nf < 8; nf++) {
        int e = nf*8 + 2*tg;
        xr0[nf] = *(const float2*)&out[(size_t)r*64 + e];
        xr1[nf] = *(const float2*)&out[(size_t)(r+8)*64 + e];
    }
    __syncthreads();

    float c[8][4];
    #pragma unroll
    for (int nf = 0; nf < 8; nf++)
        c[nf][0] = c[nf][1] = c[nf][2] = c[nf][3] = 0.f;

    #pragma unroll
    for (int ks = 0; ks < 4; ks++) {
        const int k = ks*16 + 2*tg;
        #pragma unroll
        for (int nf = 0; nf < 8; nf++) {
            const __nv_bfloat16* br = moB + (nf*8 + g)*72 + k;
            mma16816(c[nf][0], c[nf][1], c[nf][2], c[nf][3],
                     a[ks][0], a[ks][1], a[ks][2], a[ks][3],
                     *(const unsigned*)br, *(const unsigned*)(br + 8));
        }
    }

    #pragma unroll
    for (int nf = 0; nf < 8; nf++) {
        int e = nf*8 + 2*tg;
        *(float2*)&out[(size_t)r*64 + e] =
            make_float2(xr0[nf].x + c[nf][0], xr0[nf].y + c[nf][1]);
        *(float2*)&out[(size_t)(r+8)*64 + e] =
            make_float2(xr1[nf].x + c[nf][2], xr1[nf].y + c[nf][3]);
    }
}

// ============ kernel 4a: FFN GEMM1 via HMMA + fast GELU -> g_hidb ============
__global__ void __launch_bounds__(256, 2) ffn1_kernel(
    const float* __restrict__ fnw, const float* __restrict__ b1,
    const float* __restrict__ out)
{
    extern __shared__ char smc[];
    __nv_bfloat16* w1s = (__nv_bfloat16*)smc;            // [256][72]
    __nv_bfloat16* As  = (__nv_bfloat16*)(smc + 36864);  // [128][72]
    float* b1s = (float*)(smc + 36864 + 18432);          // 256
    float* fns = b1s + 256;                              // 64

    const int tid = threadIdx.x, lane = tid & 31, w = tid >> 5;
    const int g = lane >> 2, tg = lane & 3;
    const int wm = w & 3, nh = w >> 2;
    const int tok0 = blockIdx.x * 128;

    for (int i = tid; i < 256*32; i += 256) {
        int j2 = i*2;
        int o = j2 >> 6, j = j2 & 63;
        *(unsigned*)&w1s[o*72 + j] = ((const unsigned*)g_w1b)[i];
    }
    b1s[tid] = b1[tid];
    if (tid < 64) fns[tid] = fnw[tid];
    __syncthreads();

    if (tid < 128) {
        const float4* xr = (const float4*)(out + (size_t)(tok0 + tid)*64);
        float4 v[16];
        float ss = 0.f;
        #pragma unroll
        for (int i = 0; i < 16; i++) {
            v[i] = xr[i];
            ss += v[i].x*v[i].x + v[i].y*v[i].y + v[i].z*v[i].z + v[i].w*v[i].w;
        }
        float rinv = rsqrtf(ss * (1.f/64.f) + 1e-5f);
        #pragma unroll
        for (int i = 0; i < 16; i++) {
            *(unsigned*)&As[tid*72 + 4*i]     = pbf_(v[i].x*rinv*fns[4*i],   v[i].y*rinv*fns[4*i+1]);
            *(unsigned*)&As[tid*72 + 4*i + 2] = pbf_(v[i].z*rinv*fns[4*i+2], v[i].w*rinv*fns[4*i+3]);
        }
    }
    __syncthreads();

    unsigned a[4][2][4];
    #pragma unroll
    for (int ks = 0; ks < 4; ks++)
        #pragma unroll
        for (int mf = 0; mf < 2; mf++) {
            int r = wm*32 + mf*16 + g;
            int k = ks*16 + 2*tg;
            a[ks][mf][0] = *(const unsigned*)&As[ r      *72 + k];
            a[ks][mf][1] = *(const unsigned*)&As[(r + 8) *72 + k];
            a[ks][mf][2] = *(const unsigned*)&As[ r      *72 + k + 8];
            a[ks][mf][3] = *(const unsigned*)&As[(r + 8) *72 + k + 8];
        }

    #pragma unroll
    for (int ch = 0; ch < 2; ch++) {
        const int n0 = nh*128 + ch*64;
        float c[2][8][4];
        #pragma unroll
        for (int mf = 0; mf < 2; mf++)
            #pragma unroll
            for (int nf = 0; nf < 8; nf++)
                c[mf][nf][0] = c[mf][nf][1] = c[mf][nf][2] = c[mf][nf][3] = 0.f;

        #pragma unroll
        for (int ks = 0; ks < 4; ks++) {
            #pragma unroll
            for (int nf = 0; nf < 8; nf++) {
                const __nv_bfloat16* br = w1s + (n0 + nf*8 + g)*72 + ks*16 + 2*tg;
                unsigned b0 = *(const unsigned*)br;
                unsigned bq = *(const unsigned*)(br + 8);
                #pragma unroll
                for (int mf = 0; mf < 2; mf++)
                    mma16816(c[mf][nf][0], c[mf][nf][1], c[mf][nf][2], c[mf][nf][3],
                             a[ks][mf][0], a[ks][mf][1], a[ks][mf][2], a[ks][mf][3],
                             b0, bq);
            }
        }

        #pragma unroll
        for (int mf = 0; mf < 2; mf++) {
            const int r = tok0 + wm*32 + mf*16 + g;
            #pragma unroll
            for (int nf = 0; nf < 8; nf++) {
                int e = n0 + nf*8 + 2*tg;
                float be0 = b1s[e], be1 = b1s[e+1];
                *(unsigned*)&g_hidb[(size_t)r*256 + e] =
                    pbf_(gelu_(c[mf][nf][0] + be0), gelu_(c[mf][nf][1] + be1));
                *(unsigned*)&g_hidb[(size_t)(r+8)*256 + e] =
                    pbf_(gelu_(c[mf][nf][2] + be0), gelu_(c[mf][nf][3] + be1));
            }
        }
    }
}

// ============ kernel 4b: FFN GEMM2 via HMMA + residual ============
__global__ void __launch_bounds__(128, 4) ffn2_kernel(
    const float* __restrict__ b2, float* __restrict__ out)
{
    extern __shared__ char smc[];
    __nv_bfloat16* w2s = (__nv_bfloat16*)smc;   // [64][264]
    float* b2s = (float*)(smc + 64*264*2);

    const int tid = threadIdx.x, lane = tid & 31, w = tid >> 5;
    const int g = lane >> 2, tg = lane & 3;
    const int tok0 = blockIdx.x * 128;

    for (int i = tid; i < 64*128; i += 128) {
        int j2 = i*2;
        int e = j2 >> 8, o = j2 & 255;
        *(unsigned*)&w2s[e*264 + o] = ((const unsigned*)g_w2b)[i];
    }
    if (tid < 64) b2s[tid] = b2[tid];
    __syncthreads();

    float c[2][8][4];
    #pragma unroll
    for (int mf = 0; mf < 2; mf++)
        #pragma unroll
        for (int nf = 0; nf < 8; nf++)
            c[mf][nf][0] = c[mf][nf][1] = c[mf][nf][2] = c[mf][nf][3] = 0.f;

    const int m0 = tok0 + w*32;
    #pragma unroll 4
    for (int ks = 0; ks < 16; ks++) {
        const int k = ks*16 + 2*tg;
        unsigned a[2][4];
        #pragma unroll
        for (int mf = 0; mf < 2; mf++) {
            const __nv_bfloat16* ar = g_hidb + (size_t)(m0 + mf*16 + g)*256 + k;
            a[mf][0] = *(const unsigned*)ar;
            a[mf][1] = *(const unsigned*)(ar + 8*256);
            a[mf][2] = *(const unsigned*)(ar + 8);
            a[mf][3] = *(const unsigned*)(ar + 8*256 + 8);
        }
        #pragma unroll
        for (int nf = 0; nf < 8; nf++) {
            const __nv_bfloat16* br = w2s + (nf*8 + g)*264 + k;
            unsigned b0 = *(const unsigned*)br;
            unsigned bq = *(const unsigned*)(br + 8);
            #pragma unroll
            for (int mf = 0; mf < 2; mf++)
                mma16816(c[mf][nf][0], c[mf][nf][1], c[mf][nf][2], c[mf][nf][3],
                         a[mf][0], a[mf][1], a[mf][2], a[mf][3], b0, bq);
        }
    }

    #pragma unroll
    for (int mf = 0; mf < 2; mf++) {
        const int r = m0 + mf*16 + g;
        #pragma unroll
        for (int nf = 0; nf < 8; nf++) {
            int e = nf*8 + 2*tg;
            float2 o0 = *(float2*)&out[(size_t)r*64 + e];
            float2 o1 = *(float2*)&out[(size_t)(r+8)*64 + e];
            o0.x += b2s[e]   + c[mf][nf][0];
            o0.y += b2s[e+1] + c[mf][nf][1];
            o1.x += b2s[e]   + c[mf][nf][2];
            o1.y += b2s[e+1] + c[mf][nf][3];
            *(float2*)&out[(size_t)r*64 + e]     = o0;
            *(float2*)&out[(size_t)(r+8)*64 + e] = o1;
        }
    }
}

// ============ launch ============
extern "C" void kernel_launch(void* const* d_in, const int* in_sizes, int n_in,
                              void* d_out, int out_size)
{
    const float* x     = (const float*)d_in[0];
    const float* maddr = (const float*)d_in[1];
    const float* mvals = (const float*)d_in[2];
    const float* anw   = (const float*)d_in[3];
    const float* wq    = (const float*)d_in[4];
    const float* wk    = (const float*)d_in[5];
    const float* wv    = (const float*)d_in[6];
    const float* wo    = (const float*)d_in[7];
    const float* mnw   = (const float*)d_in[8];
    const float* mq    = (const float*)d_in[9];
    const float* mo    = (const float*)d_in[10];
    const float* fnw   = (const float*)d_in[11];
    const float* w1    = (const float*)d_in[12];
    const float* b1    = (const float*)d_in[13];
    const float* w2    = (const float*)d_in[14];
    const float* b2    = (const float*)d_in[15];
    float* out = (float*)d_out;

    const int QKV_SMEM  = 27648 + 18432 + 256;                    // 46,336
    const int ATT_SMEM  = 32768 + 33024 + 4096;                   // 69,888
    const int MEM1_SMEM = 64*72*2;                                // 9,216
    const int MEM2_SMEM = (2112 + 2080 + 64) * 4 + 8*96*8;        // 23,168
    const int FFN1_SMEM = 36864 + 18432 + (256 + 64) * 4;         // 56,576
    const int FFN2_SMEM = 64*264*2 + 64*4;                        // 34,048

    cudaFuncSetAttribute(qkv_kernel, cudaFuncAttributeMaxDynamicSharedMemorySize, QKV_SMEM);
    cudaFuncSetAttribute(attn_kernel, cudaFuncAttributeMaxDynamicSharedMemorySize, ATT_SMEM);
    cudaFuncSetAttribute(mem1_kernel, cudaFuncAttributeMaxDynamicSharedMemorySize, MEM1_SMEM);
    cudaFuncSetAttribute(mem2_kernel, cudaFuncAttributeMaxDynamicSharedMemorySize, MEM2_SMEM);
    cudaFuncSetAttribute(mem3_kernel, cudaFuncAttributeMaxDynamicSharedMemorySize, MEM1_SMEM);
    cudaFuncSetAttribute(ffn1_kernel, cudaFuncAttributeMaxDynamicSharedMemorySize, FFN1_SMEM);
    cudaFuncSetAttribute(ffn2_kernel, cudaFuncAttributeMaxDynamicSharedMemorySize, FFN2_SMEM);

    cvt_kernel<<<64, 256>>>(w1, w2, wo, mo);
    qkv_kernel<<<256, 256, QKV_SMEM>>>(x, anw, wq, wk, wv);
    attn_kernel<<<1024, 128, ATT_SMEM>>>();
    mem1_kernel<<<256, 256, MEM1_SMEM>>>(x, out);
    mem2_kernel<<<592, 256, MEM2_SMEM>>>(mvals, maddr, mnw, mq, out);
    mem3_kernel<<<256, 256, MEM1_SMEM>>>(out);
    ffn1_kernel<<<256, 256, FFN1_SMEM>>>(fnw, b1, out);
    ffn2_kernel<<<256, 128, FFN2_SMEM>>>(b2, out);
}